// round 2
// baseline (speedup 1.0000x reference)
#include <cuda_runtime.h>

// Fixed problem dims (verified against metadata: hidden (4,4096,1280) f32, enc (4,85,2048) f32)
#define B_   4
#define S_   4096
#define C_   1280
#define DC_  2048
#define H_   20
#define D_   64
#define LTXT 77
#define LIMG 4
#define LLBL 4
#define LTOT 85
#define KPAD 65   // smem row stride for K/V tiles (conflict-free)

// ---------------------------------------------------------------------------
// Scratch (device globals: allocation inside kernel_launch is forbidden)
// ---------------------------------------------------------------------------
__device__ float g_q[(size_t)B_ * S_ * C_];     // 84 MB
__device__ float g_attn[(size_t)B_ * S_ * C_];  // 84 MB
__device__ float g_k[(size_t)B_ * LTOT * C_];   // 1.7 MB
__device__ float g_v[(size_t)B_ * LTOT * C_];   // 1.7 MB

// ---------------------------------------------------------------------------
// 128x128x8 fp32 SGEMM, 256 threads, 8x8 per thread.
// C[z] = A[z] @ Bw (+ bias) (+ resid[z]).  A: MxK row-major, Bw: KxN row-major.
// Requires: K % 8 == 0, N % 128 == 0 (true for all our launches). M guarded.
// ---------------------------------------------------------------------------
__global__ __launch_bounds__(256)
void sgemm128(const float* __restrict__ Abase,
              const float* __restrict__ Bw,
              float* __restrict__ Cbase,
              int M, int N, int K,
              long long strideA, long long strideC,
              const float* __restrict__ bias,
              const float* __restrict__ resid)
{
    __shared__ float As[8][128];
    __shared__ float Bs[8][128];

    const float* A = Abase + (long long)blockIdx.z * strideA;
    float*       C = Cbase + (long long)blockIdx.z * strideC;
    const float* R = resid ? (resid + (long long)blockIdx.z * strideC) : resid;

    const int bm  = blockIdx.y * 128;
    const int bn  = blockIdx.x * 128;
    const int tid = threadIdx.x;
    const int tx  = tid & 15;      // 0..15 -> col block of 8
    const int ty  = tid >> 4;      // 0..15 -> row block of 8

    const int aRow = tid >> 1;            // 0..127
    const int aCol = (tid & 1) << 2;      // 0 or 4
    const int bRow = tid >> 5;            // 0..7
    const int bCol = (tid & 31) << 2;     // 0..124

    float acc[8][8];
#pragma unroll
    for (int i = 0; i < 8; i++)
#pragma unroll
        for (int j = 0; j < 8; j++) acc[i][j] = 0.f;

    for (int k0 = 0; k0 < K; k0 += 8) {
        float4 av = make_float4(0.f, 0.f, 0.f, 0.f);
        if (bm + aRow < M)
            av = *(const float4*)(A + (long long)(bm + aRow) * K + k0 + aCol);
        As[aCol + 0][aRow] = av.x;
        As[aCol + 1][aRow] = av.y;
        As[aCol + 2][aRow] = av.z;
        As[aCol + 3][aRow] = av.w;

        float4 bv = *(const float4*)(Bw + (long long)(k0 + bRow) * N + bn + bCol);
        *(float4*)&Bs[bRow][bCol] = bv;
        __syncthreads();

#pragma unroll
        for (int kk = 0; kk < 8; kk++) {
            float a[8], b[8];
            *(float4*)&a[0] = *(const float4*)&As[kk][ty * 8];
            *(float4*)&a[4] = *(const float4*)&As[kk][ty * 8 + 4];
            *(float4*)&b[0] = *(const float4*)&Bs[kk][tx * 8];
            *(float4*)&b[4] = *(const float4*)&Bs[kk][tx * 8 + 4];
#pragma unroll
            for (int i = 0; i < 8; i++)
#pragma unroll
                for (int j = 0; j < 8; j++)
                    acc[i][j] = fmaf(a[i], b[j], acc[i][j]);
        }
        __syncthreads();
    }

#pragma unroll
    for (int i = 0; i < 8; i++) {
        const int r = bm + ty * 8 + i;
        if (r < M) {
#pragma unroll
            for (int j4 = 0; j4 < 8; j4 += 4) {
                const int c = bn + tx * 8 + j4;
                float4 o;
                o.x = acc[i][j4 + 0]; o.y = acc[i][j4 + 1];
                o.z = acc[i][j4 + 2]; o.w = acc[i][j4 + 3];
                if (bias) {
                    o.x += bias[c]; o.y += bias[c + 1];
                    o.z += bias[c + 2]; o.w += bias[c + 3];
                }
                if (R) {
                    const float4 rv = *(const float4*)(R + (long long)r * N + c);
                    o.x += rv.x; o.y += rv.y; o.z += rv.z; o.w += rv.w;
                }
                *(float4*)(C + (long long)r * N + c) = o;
            }
        }
    }
}

// ---------------------------------------------------------------------------
// Thin GEMM for the small K/V projections (M = 77 or 4 per batch slice).
// BM=32, BN=64, BK=32, 256 threads, 2x4 per thread. Grid: (N/64, ceil(M/32), B).
// Requires: K % 32 == 0, N % 64 == 0. M guarded.
// ---------------------------------------------------------------------------
__global__ __launch_bounds__(256)
void sgemm32(const float* __restrict__ Abase,
             const float* __restrict__ Bw,
             float* __restrict__ Cbase,
             int M, int N, int K,
             long long strideA, long long strideC)
{
    __shared__ float As[32][33];
    __shared__ float Bs[32][64];

    const float* A = Abase + (long long)blockIdx.z * strideA;
    float*       C = Cbase + (long long)blockIdx.z * strideC;

    const int bm  = blockIdx.y * 32;
    const int bn  = blockIdx.x * 64;
    const int tid = threadIdx.x;
    const int tx  = tid & 15;   // col group (4 cols)
    const int ty  = tid >> 4;   // row group (2 rows)

    const int aRow = tid >> 3;            // 0..31
    const int aCol = (tid & 7) << 2;      // 0..28
    const int bRow = tid >> 4;            // 0..15 (two passes: +16)
    const int bCol = (tid & 15) << 2;     // 0..60

    float acc[2][4];
#pragma unroll
    for (int i = 0; i < 2; i++)
#pragma unroll
        for (int j = 0; j < 4; j++) acc[i][j] = 0.f;

    for (int k0 = 0; k0 < K; k0 += 32) {
        float4 av = make_float4(0.f, 0.f, 0.f, 0.f);
        if (bm + aRow < M)
            av = *(const float4*)(A + (long long)(bm + aRow) * K + k0 + aCol);
        As[aCol + 0][aRow] = av.x;
        As[aCol + 1][aRow] = av.y;
        As[aCol + 2][aRow] = av.z;
        As[aCol + 3][aRow] = av.w;

#pragma unroll
        for (int p = 0; p < 2; p++) {
            const int r = bRow + p * 16;
            float4 bv = *(const float4*)(Bw + (long long)(k0 + r) * N + bn + bCol);
            *(float4*)&Bs[r][bCol] = bv;
        }
        __syncthreads();

#pragma unroll
        for (int kk = 0; kk < 32; kk++) {
            const float a0 = As[kk][ty * 2];
            const float a1 = As[kk][ty * 2 + 1];
            float4 b = *(const float4*)&Bs[kk][tx * 4];
            acc[0][0] = fmaf(a0, b.x, acc[0][0]);
            acc[0][1] = fmaf(a0, b.y, acc[0][1]);
            acc[0][2] = fmaf(a0, b.z, acc[0][2]);
            acc[0][3] = fmaf(a0, b.w, acc[0][3]);
            acc[1][0] = fmaf(a1, b.x, acc[1][0]);
            acc[1][1] = fmaf(a1, b.y, acc[1][1]);
            acc[1][2] = fmaf(a1, b.z, acc[1][2]);
            acc[1][3] = fmaf(a1, b.w, acc[1][3]);
        }
        __syncthreads();
    }

#pragma unroll
    for (int i = 0; i < 2; i++) {
        const int r = bm + ty * 2 + i;
        if (r < M) {
            const int c = bn + tx * 4;
            float4 o;
            o.x = acc[i][0]; o.y = acc[i][1]; o.z = acc[i][2]; o.w = acc[i][3];
            *(float4*)(C + (long long)r * N + c) = o;
        }
    }
}

// ---------------------------------------------------------------------------
// Fused 3-branch cross-attention. One block per (b*H + h, s-chunk).
// K/V for all 85 keys of this (b,h) live in SMEM. One warp = one query at a
// time: text softmax (77 keys) split across lanes + warp reductions;
// img/lbl softmaxes (4 keys each) computed redundantly per-lane (exact).
// ---------------------------------------------------------------------------
__global__ __launch_bounds__(256)
void attn_kernel(const float* __restrict__ q,     // (B,S,C)
                 const float* __restrict__ kall,  // (B,85,C)
                 const float* __restrict__ vall,  // (B,85,C)
                 float* __restrict__ outp)        // (B,S,C)
{
    __shared__ float Ksh[LTOT * KPAD];
    __shared__ float Vsh[LTOT * KPAD];
    __shared__ float Psh[8][LTXT];

    const int bh   = blockIdx.x;
    const int b    = bh / H_;
    const int h    = bh % H_;
    const int tid  = threadIdx.x;
    const int lane = tid & 31;
    const int warp = tid >> 5;

    for (int i = tid; i < LTOT * D_; i += 256) {
        const int l = i >> 6;
        const int d = i & 63;
        const long long g = ((long long)b * LTOT + l) * C_ + h * D_ + d;
        Ksh[l * KPAD + d] = kall[g];
        Vsh[l * KPAD + d] = vall[g];
    }
    __syncthreads();

    const int sPer = S_ / gridDim.y;
    const int s0   = blockIdx.y * sPer;
    const float scale = 0.125f;  // 64^-0.5

    for (int s = s0 + warp; s < s0 + sPer; s += 8) {
        const float* qp = q + ((long long)b * S_ + s) * C_ + h * D_;
        float qv[D_];
#pragma unroll
        for (int i = 0; i < D_ / 4; i++) {
            float4 t = *(const float4*)(qp + i * 4);
            qv[i * 4 + 0] = t.x; qv[i * 4 + 1] = t.y;
            qv[i * 4 + 2] = t.z; qv[i * 4 + 3] = t.w;
        }

        // --- text branch: keys {lane, lane+32, lane+64 (if <77)} ---
        const bool v2 = (lane < LTXT - 64);  // lane < 13
        float sc0 = 0.f, sc1 = 0.f, sc2 = 0.f;
        {
            const float* k0p = &Ksh[lane * KPAD];
            const float* k1p = &Ksh[(lane + 32) * KPAD];
            const float* k2p = &Ksh[(v2 ? lane + 64 : lane) * KPAD];
#pragma unroll
            for (int d = 0; d < D_; d++) {
                sc0 = fmaf(qv[d], k0p[d], sc0);
                sc1 = fmaf(qv[d], k1p[d], sc1);
                sc2 = fmaf(qv[d], k2p[d], sc2);
            }
        }
        sc0 *= scale; sc1 *= scale; sc2 *= scale;
        float m = fmaxf(sc0, sc1);
        if (v2) m = fmaxf(m, sc2);
#pragma unroll
        for (int off = 16; off > 0; off >>= 1)
            m = fmaxf(m, __shfl_xor_sync(0xffffffffu, m, off));
        const float e0 = __expf(sc0 - m);
        const float e1 = __expf(sc1 - m);
        const float e2 = v2 ? __expf(sc2 - m) : 0.f;
        float lsum = e0 + e1 + e2;
#pragma unroll
        for (int off = 16; off > 0; off >>= 1)
            lsum += __shfl_xor_sync(0xffffffffu, lsum, off);
        const float invT = 1.f / lsum;
        Psh[warp][lane]      = e0;
        Psh[warp][lane + 32] = e1;
        if (v2) Psh[warp][lane + 64] = e2;
        __syncwarp();

        // --- img / lbl branches: 4 keys each, computed redundantly per lane ---
        float pi[4], pl[4];
        {
            float si[4], sl[4];
#pragma unroll
            for (int kk = 0; kk < 4; kk++) { si[kk] = 0.f; sl[kk] = 0.f; }
#pragma unroll
            for (int kk = 0; kk < 4; kk++) {
                const float* kp = &Ksh[(LTXT + kk) * KPAD];
                const float* lp = &Ksh[(LTXT + 4 + kk) * KPAD];
#pragma unroll
                for (int d = 0; d < D_; d++) {
                    si[kk] = fmaf(qv[d], kp[d], si[kk]);
                    sl[kk] = fmaf(qv[d], lp[d], sl[kk]);
                }
            }
            float mi = -1e30f, ml = -1e30f;
#pragma unroll
            for (int kk = 0; kk < 4; kk++) {
                si[kk] *= scale; sl[kk] *= scale;
                mi = fmaxf(mi, si[kk]); ml = fmaxf(ml, sl[kk]);
            }
            float sumi = 0.f, suml = 0.f;
#pragma unroll
            for (int kk = 0; kk < 4; kk++) {
                pi[kk] = __expf(si[kk] - mi); pl[kk] = __expf(sl[kk] - ml);
                sumi += pi[kk]; suml += pl[kk];
            }
            const float ri = 1.f / sumi, rl = 1.f / suml;
#pragma unroll
            for (int kk = 0; kk < 4; kk++) { pi[kk] *= ri; pl[kk] *= rl; }
        }

        // --- output: lane owns d = lane and d = lane+32 ---
        float o0 = 0.f, o1 = 0.f;
        for (int k2 = 0; k2 < LTXT; k2++) {
            const float p = Psh[warp][k2];
            o0 = fmaf(p, Vsh[k2 * KPAD + lane], o0);
            o1 = fmaf(p, Vsh[k2 * KPAD + lane + 32], o1);
        }
        o0 *= invT; o1 *= invT;
#pragma unroll
        for (int kk = 0; kk < 4; kk++) {
            o0 = fmaf(pi[kk], Vsh[(LTXT + kk) * KPAD + lane], o0);
            o1 = fmaf(pi[kk], Vsh[(LTXT + kk) * KPAD + lane + 32], o1);
            o0 = fmaf(pl[kk], Vsh[(LTXT + 4 + kk) * KPAD + lane], o0);
            o1 = fmaf(pl[kk], Vsh[(LTXT + 4 + kk) * KPAD + lane + 32], o1);
        }
        float* op = outp + ((long long)b * S_ + s) * C_ + h * D_;
        op[lane]      = o0;
        op[lane + 32] = o1;
        __syncwarp();
    }
}

// ---------------------------------------------------------------------------
// Launch: q-proj -> 6 kv-projs -> attention -> o-proj(+bias+residual)
// ---------------------------------------------------------------------------
extern "C" void kernel_launch(void* const* d_in, const int* in_sizes, int n_in,
                              void* d_out, int out_size)
{
    const float* hidden = (const float*)d_in[0];
    const float* enc    = (const float*)d_in[1];
    const float* Wq     = (const float*)d_in[2];
    const float* Wk     = (const float*)d_in[3];
    const float* Wv     = (const float*)d_in[4];
    const float* Wk_ip  = (const float*)d_in[5];
    const float* Wv_ip  = (const float*)d_in[6];
    const float* Wk_lbl = (const float*)d_in[7];
    const float* Wv_lbl = (const float*)d_in[8];
    const float* Wo     = (const float*)d_in[9];
    const float* bo     = (const float*)d_in[10];
    float* out = (float*)d_out;

    float *qb, *ab, *kb, *vb;
    cudaGetSymbolAddress((void**)&qb, g_q);
    cudaGetSymbolAddress((void**)&ab, g_attn);
    cudaGetSymbolAddress((void**)&kb, g_k);
    cudaGetSymbolAddress((void**)&vb, g_v);

    const dim3 blk(256);

    // Q projection: (B*S, C) = hidden @ Wq
    {
        dim3 grid(C_ / 128, (B_ * S_) / 128, 1);
        sgemm128<<<grid, blk>>>(hidden, Wq, qb, B_ * S_, C_, C_, 0, 0,
                                nullptr, nullptr);
    }

    // K/V projections into rows [0,77), [77,81), [81,85) of g_k / g_v
    {
        const long long sA = (long long)LTOT * DC_;
        const long long sC = (long long)LTOT * C_;
        dim3 gT(C_ / 64, (LTXT + 31) / 32, B_);
        dim3 gS(C_ / 64, 1, B_);
        sgemm32<<<gT, blk>>>(enc, Wk, kb, LTXT, C_, DC_, sA, sC);
        sgemm32<<<gT, blk>>>(enc, Wv, vb, LTXT, C_, DC_, sA, sC);
        sgemm32<<<gS, blk>>>(enc + (long long)LTXT * DC_, Wk_ip,
                             kb + (long long)LTXT * C_, LIMG, C_, DC_, sA, sC);
        sgemm32<<<gS, blk>>>(enc + (long long)LTXT * DC_, Wv_ip,
                             vb + (long long)LTXT * C_, LIMG, C_, DC_, sA, sC);
        sgemm32<<<gS, blk>>>(enc + (long long)(LTXT + LIMG) * DC_, Wk_lbl,
                             kb + (long long)(LTXT + LIMG) * C_, LLBL, C_, DC_, sA, sC);
        sgemm32<<<gS, blk>>>(enc + (long long)(LTXT + LIMG) * DC_, Wv_lbl,
                             vb + (long long)(LTXT + LIMG) * C_, LLBL, C_, DC_, sA, sC);
    }

    // Fused 3-branch attention
    {
        dim3 grid(B_ * H_, 8);
        attn_kernel<<<grid, blk>>>(qb, kb, vb, ab);
    }

    // Output projection + bias + residual
    {
        dim3 grid(C_ / 128, (B_ * S_) / 128, 1);
        sgemm128<<<grid, blk>>>(ab, Wo, out, B_ * S_, C_, C_, 0, 0,
                                bo, hidden);
    }
}

// round 5
// speedup vs baseline: 1.7331x; 1.7331x over previous
#include <cuda_runtime.h>
#include <cuda_bf16.h>
#include <cstdint>

// Problem dims
#define B_   4
#define S_   4096
#define C_   1280
#define DC_  2048
#define H_   20
#define D_   64
#define LTXT 77
#define LIMG 4
#define LLBL 4
#define LTOT 85
#define KPAD 65
#define MTOT (B_ * S_)   // 16384

// ---------------------------------------------------------------------------
// Device scratch
// ---------------------------------------------------------------------------
__device__ float g_q[(size_t)MTOT * C_];                    // fp32 Q for attention
__device__ __nv_bfloat16 g_ahi[(size_t)MTOT * C_];          // activation hi
__device__ __nv_bfloat16 g_alo[(size_t)MTOT * C_];          // activation lo
__device__ __nv_bfloat16 g_wqhi[(size_t)C_ * C_];           // Wq^T hi  [N,K]
__device__ __nv_bfloat16 g_wqlo[(size_t)C_ * C_];
__device__ __nv_bfloat16 g_wohi[(size_t)C_ * C_];           // Wo^T hi
__device__ __nv_bfloat16 g_wolo[(size_t)C_ * C_];
__device__ float g_k[(size_t)B_ * LTOT * C_];
__device__ float g_v[(size_t)B_ * LTOT * C_];

// ---------------------------------------------------------------------------
// small PTX helpers (all stable-ISA, sm_80+: ldmatrix / mma.sync / cp.async)
// ---------------------------------------------------------------------------
__device__ __forceinline__ uint32_t smem_u32(const void* p) {
    uint32_t a;
    asm("{ .reg .u64 t; cvta.to.shared.u64 t, %1; cvt.u32.u64 %0, t; }"
        : "=r"(a) : "l"(p));
    return a;
}

__device__ __forceinline__ void cp_async16(uint32_t dst, const void* src) {
    asm volatile("cp.async.cg.shared.global [%0], [%1], 16;"
                 :: "r"(dst), "l"(src));
}
__device__ __forceinline__ void cp_commit() {
    asm volatile("cp.async.commit_group;");
}
__device__ __forceinline__ void cp_wait0() {
    asm volatile("cp.async.wait_group 0;");
}

__device__ __forceinline__ void ldsm_x4(uint32_t* r, uint32_t addr) {
    asm volatile("ldmatrix.sync.aligned.m8n8.x4.shared.b16 {%0,%1,%2,%3}, [%4];"
                 : "=r"(r[0]), "=r"(r[1]), "=r"(r[2]), "=r"(r[3]) : "r"(addr));
}
__device__ __forceinline__ void ldsm_x2(uint32_t* r, uint32_t addr) {
    asm volatile("ldmatrix.sync.aligned.m8n8.x2.shared.b16 {%0,%1}, [%2];"
                 : "=r"(r[0]), "=r"(r[1]) : "r"(addr));
}

__device__ __forceinline__ void mma_bf16(float* c, const uint32_t* a,
                                         const uint32_t* b) {
    asm volatile(
        "mma.sync.aligned.m16n8k16.row.col.f32.bf16.bf16.f32 "
        "{%0,%1,%2,%3}, {%4,%5,%6,%7}, {%8,%9}, {%0,%1,%2,%3};"
        : "+f"(c[0]), "+f"(c[1]), "+f"(c[2]), "+f"(c[3])
        : "r"(a[0]), "r"(a[1]), "r"(a[2]), "r"(a[3]), "r"(b[0]), "r"(b[1]));
}

// ---------------------------------------------------------------------------
// Conversion kernels
// ---------------------------------------------------------------------------
__global__ void conv_split(const float* __restrict__ src,
                           __nv_bfloat16* __restrict__ hi,
                           __nv_bfloat16* __restrict__ lo, long long n4) {
    long long i = (long long)blockIdx.x * blockDim.x + threadIdx.x;
    if (i >= n4) return;
    float4 v = ((const float4*)src)[i];
    __nv_bfloat16 h[4], l[4];
    float f[4] = {v.x, v.y, v.z, v.w};
#pragma unroll
    for (int j = 0; j < 4; j++) {
        h[j] = __float2bfloat16(f[j]);
        l[j] = __float2bfloat16(f[j] - __bfloat162float(h[j]));
    }
    ((uint2*)hi)[i] = *(uint2*)h;
    ((uint2*)lo)[i] = *(uint2*)l;
}

// W (K x N fp32, row-major) -> Wt hi/lo (N x K bf16, K contiguous)
__global__ void conv_w_t(const float* __restrict__ W,
                         __nv_bfloat16* __restrict__ Thi,
                         __nv_bfloat16* __restrict__ Tlo) {
    __shared__ float t[32][33];
    const int n0 = blockIdx.x * 32, k0 = blockIdx.y * 32;
    const int tx = threadIdx.x, ty = threadIdx.y;  // 32 x 8
#pragma unroll
    for (int i = 0; i < 4; i++) {
        const int kk = ty + 8 * i;
        t[kk][tx] = W[(long long)(k0 + kk) * C_ + n0 + tx];
    }
    __syncthreads();
#pragma unroll
    for (int i = 0; i < 4; i++) {
        const int nn = ty + 8 * i;
        const float v = t[tx][nn];
        const __nv_bfloat16 h = __float2bfloat16(v);
        const long long o = (long long)(n0 + nn) * C_ + k0 + tx;
        Thi[o] = h;
        Tlo[o] = __float2bfloat16(v - __bfloat162float(h));
    }
}

// ---------------------------------------------------------------------------
// bf16 split-precision GEMM via mma.sync (HMMA), fp32 accumulate.
// D[M,N] = (Ahi+Alo)[M,K] @ (Bhi+Blo)^T[N,K]  (3 products)
// CTA 128x128, BK=32, 8 warps (warp tile 64x32), padded smem rows (40 bf16),
// cp.async 2-stage pipeline. Grid (N/128, M/128). Optional bias+residual.
// ---------------------------------------------------------------------------
#define GK    C_            // 1280
#define NIT   (GK / 32)     // 40
#define ROWB  40            // bf16 elems per smem row (32 + 8 pad) -> 80 bytes
#define TILEB (128 * ROWB * 2)          // 10240 bytes per tile
#define STAGEB (4 * TILEB)              // Ahi, Alo, Bhi, Blo
#define SMEM_GEMM (2 * STAGEB)          // 81920 bytes

__device__ __forceinline__ void gemm_issue_stage(
    uint32_t sbase, const __nv_bfloat16* Ahi, const __nv_bfloat16* Alo,
    const __nv_bfloat16* Bhi, const __nv_bfloat16* Blo,
    int bm, int bn, int k0, int tid)
{
    const __nv_bfloat16* srcs[4] = {Ahi + (long long)bm * GK,
                                    Alo + (long long)bm * GK,
                                    Bhi + (long long)bn * GK,
                                    Blo + (long long)bn * GK};
#pragma unroll
    for (int t = 0; t < 4; t++) {
#pragma unroll
        for (int i = 0; i < 2; i++) {
            const int c   = tid + 256 * i;       // 0..511
            const int row = c >> 2;
            const int ch  = c & 3;
            const void* src = srcs[t] + (long long)row * GK + k0 + ch * 8;
            cp_async16(sbase + t * TILEB + row * (ROWB * 2) + ch * 16, src);
        }
    }
    cp_commit();
}

__global__ __launch_bounds__(256, 1)
void gemm_mma(const __nv_bfloat16* __restrict__ Ahi,
              const __nv_bfloat16* __restrict__ Alo,
              const __nv_bfloat16* __restrict__ Bhi,
              const __nv_bfloat16* __restrict__ Blo,
              float* __restrict__ Cout,
              const float* __restrict__ bias,
              const float* __restrict__ resid)
{
    extern __shared__ char smem[];
    const int tid  = threadIdx.x;
    const int warp = tid >> 5;
    const int lane = tid & 31;
    const int bm   = blockIdx.y * 128;
    const int bn   = blockIdx.x * 128;
    const uint32_t sb = smem_u32(smem);

    const int wm = (warp >> 2) * 64;   // warp M offset (0 or 64)
    const int wn = (warp & 3) * 32;    // warp N offset (0,32,64,96)

    float acc[4][4][4];
#pragma unroll
    for (int i = 0; i < 4; i++)
#pragma unroll
        for (int j = 0; j < 4; j++)
#pragma unroll
            for (int e = 0; e < 4; e++) acc[i][j][e] = 0.f;

    // ldmatrix lane address components
    const int lmat = lane >> 3;   // 0..3
    const int lrow = lane & 7;
    // A (x4): row = wm + i*16 + (lmat&1)*8 + lrow, kcol = ks*16 + (lmat>>1)*8
    const int aRow  = (lmat & 1) * 8 + lrow;
    const int aKoff = (lmat >> 1) * 8;
    // B (x2): row = wn + j*8 + lrow2, kcol = ks*16 + bmat*8
    const int bmat  = lmat & 1;
    const int bRow  = lrow;

    gemm_issue_stage(sb, Ahi, Alo, Bhi, Blo, bm, bn, 0, tid);

    for (int it = 0; it < NIT; it++) {
        cp_wait0();
        __syncthreads();
        if (it + 1 < NIT)
            gemm_issue_stage(sb + ((it + 1) & 1) * STAGEB,
                             Ahi, Alo, Bhi, Blo, bm, bn, (it + 1) * 32, tid);

        const uint32_t st = sb + (it & 1) * STAGEB;
        const uint32_t sAh = st, sAl = st + TILEB;
        const uint32_t sBh = st + 2 * TILEB, sBl = st + 3 * TILEB;

#pragma unroll
        for (int ks = 0; ks < 2; ks++) {
            uint32_t ah[4][4], al[4][4], bh[4][2], bl[4][2];
#pragma unroll
            for (int i = 0; i < 4; i++) {
                const uint32_t off =
                    (uint32_t)(wm + i * 16 + aRow) * (ROWB * 2) +
                    (uint32_t)(ks * 16 + aKoff) * 2;
                ldsm_x4(ah[i], sAh + off);
                ldsm_x4(al[i], sAl + off);
            }
#pragma unroll
            for (int j = 0; j < 4; j++) {
                const uint32_t off =
                    (uint32_t)(wn + j * 8 + bRow) * (ROWB * 2) +
                    (uint32_t)(ks * 16 + bmat * 8) * 2;
                ldsm_x2(bh[j], sBh + off);
                ldsm_x2(bl[j], sBl + off);
            }
#pragma unroll
            for (int i = 0; i < 4; i++)
#pragma unroll
                for (int j = 0; j < 4; j++) {
                    mma_bf16(acc[i][j], ah[i], bh[j]);
                    mma_bf16(acc[i][j], ah[i], bl[j]);
                    mma_bf16(acc[i][j], al[i], bh[j]);
                }
        }
        __syncthreads();
    }

    // epilogue: acc -> gmem fp32 (+bias)(+resid)
#pragma unroll
    for (int i = 0; i < 4; i++) {
#pragma unroll
        for (int j = 0; j < 4; j++) {
            const int col = bn + wn + j * 8 + (lane & 3) * 2;
#pragma unroll
            for (int half = 0; half < 2; half++) {
                const long long row = bm + wm + i * 16 + (lane >> 2) + half * 8;
                float2 o;
                o.x = acc[i][j][half * 2 + 0];
                o.y = acc[i][j][half * 2 + 1];
                if (bias) { o.x += bias[col]; o.y += bias[col + 1]; }
                if (resid) {
                    const float2 rv = *(const float2*)(resid + row * C_ + col);
                    o.x += rv.x; o.y += rv.y;
                }
                *(float2*)(Cout + row * C_ + col) = o;
            }
        }
    }
}

// ---------------------------------------------------------------------------
// Split-K thin GEMM for the KV projections (atomicAdd into zeroed output).
// BM=32, BN=64, K-chunk = DC_/8 = 256. Grid: (C_/64, rowTiles*KSPLIT, B_).
// ---------------------------------------------------------------------------
#define KSPLIT 8
#define KCHUNK (DC_ / KSPLIT)

__global__ __launch_bounds__(256)
void sgemm32s(const float* __restrict__ Abase,
              const float* __restrict__ Bw,
              float* __restrict__ Cbase,
              int M, long long strideA, long long strideC) {
    __shared__ float As[32][33];
    __shared__ float Bs[32][64];

    const float* A = Abase + (long long)blockIdx.z * strideA;
    float*       Cc = Cbase + (long long)blockIdx.z * strideC;

    const int rt = blockIdx.y / KSPLIT;
    const int ks = blockIdx.y % KSPLIT;
    const int bm = rt * 32;
    const int bn = blockIdx.x * 64;
    const int kc0 = ks * KCHUNK;

    const int tid = threadIdx.x;
    const int tx = tid & 15, ty = tid >> 4;
    const int aRow = tid >> 3, aCol = (tid & 7) << 2;
    const int bRow = tid >> 4, bCol = (tid & 15) << 2;

    float acc[2][4];
#pragma unroll
    for (int i = 0; i < 2; i++)
#pragma unroll
        for (int j = 0; j < 4; j++) acc[i][j] = 0.f;

    for (int k0 = kc0; k0 < kc0 + KCHUNK; k0 += 32) {
        float4 av = make_float4(0.f, 0.f, 0.f, 0.f);
        if (bm + aRow < M)
            av = *(const float4*)(A + (long long)(bm + aRow) * DC_ + k0 + aCol);
        As[aCol + 0][aRow] = av.x;
        As[aCol + 1][aRow] = av.y;
        As[aCol + 2][aRow] = av.z;
        As[aCol + 3][aRow] = av.w;
#pragma unroll
        for (int p = 0; p < 2; p++) {
            const int r = bRow + p * 16;
            *(float4*)&Bs[r][bCol] =
                *(const float4*)(Bw + (long long)(k0 + r) * C_ + bn + bCol);
        }
        __syncthreads();
#pragma unroll
        for (int kk = 0; kk < 32; kk++) {
            const float a0 = As[kk][ty * 2];
            const float a1 = As[kk][ty * 2 + 1];
            const float4 b = *(const float4*)&Bs[kk][tx * 4];
            acc[0][0] = fmaf(a0, b.x, acc[0][0]);
            acc[0][1] = fmaf(a0, b.y, acc[0][1]);
            acc[0][2] = fmaf(a0, b.z, acc[0][2]);
            acc[0][3] = fmaf(a0, b.w, acc[0][3]);
            acc[1][0] = fmaf(a1, b.x, acc[1][0]);
            acc[1][1] = fmaf(a1, b.y, acc[1][1]);
            acc[1][2] = fmaf(a1, b.z, acc[1][2]);
            acc[1][3] = fmaf(a1, b.w, acc[1][3]);
        }
        __syncthreads();
    }

#pragma unroll
    for (int i = 0; i < 2; i++) {
        const int r = bm + ty * 2 + i;
        if (r < M) {
            float* cp = Cc + (long long)r * C_ + bn + tx * 4;
#pragma unroll
            for (int j = 0; j < 4; j++) atomicAdd(cp + j, acc[i][j]);
        }
    }
}

// ---------------------------------------------------------------------------
// Fused 3-branch cross-attention; writes bf16 hi/lo output for the O-proj.
// ---------------------------------------------------------------------------
__global__ __launch_bounds__(256)
void attn_kernel(const float* __restrict__ q,
                 const float* __restrict__ kall,
                 const float* __restrict__ vall,
                 __nv_bfloat16* __restrict__ ohi,
                 __nv_bfloat16* __restrict__ olo) {
    __shared__ float Ksh[LTOT * KPAD];
    __shared__ float Vsh[LTOT * KPAD];
    __shared__ float Psh[8][LTXT];

    const int bh = blockIdx.x;
    const int b = bh / H_, h = bh % H_;
    const int tid = threadIdx.x, lane = tid & 31, warp = tid >> 5;

    for (int i = tid; i < LTOT * D_; i += 256) {
        const int l = i >> 6, d = i & 63;
        const long long g = ((long long)b * LTOT + l) * C_ + h * D_ + d;
        Ksh[l * KPAD + d] = kall[g];
        Vsh[l * KPAD + d] = vall[g];
    }
    __syncthreads();

    const int sPer = S_ / gridDim.y;
    const int s0 = blockIdx.y * sPer;
    const float scale = 0.125f;

    for (int s = s0 + warp; s < s0 + sPer; s += 8) {
        const float* qp = q + ((long long)b * S_ + s) * C_ + h * D_;
        float qv[D_];
#pragma unroll
        for (int i = 0; i < D_ / 4; i++) {
            float4 t = *(const float4*)(qp + i * 4);
            qv[i * 4 + 0] = t.x; qv[i * 4 + 1] = t.y;
            qv[i * 4 + 2] = t.z; qv[i * 4 + 3] = t.w;
        }

        const bool v2 = (lane < LTXT - 64);
        float sc0 = 0.f, sc1 = 0.f, sc2 = 0.f;
        {
            const float* k0p = &Ksh[lane * KPAD];
            const float* k1p = &Ksh[(lane + 32) * KPAD];
            const float* k2p = &Ksh[(v2 ? lane + 64 : lane) * KPAD];
#pragma unroll
            for (int d = 0; d < D_; d++) {
                sc0 = fmaf(qv[d], k0p[d], sc0);
                sc1 = fmaf(qv[d], k1p[d], sc1);
                sc2 = fmaf(qv[d], k2p[d], sc2);
            }
        }
        sc0 *= scale; sc1 *= scale; sc2 *= scale;
        float m = fmaxf(sc0, sc1);
        if (v2) m = fmaxf(m, sc2);
#pragma unroll
        for (int off = 16; off > 0; off >>= 1)
            m = fmaxf(m, __shfl_xor_sync(0xffffffffu, m, off));
        const float e0 = __expf(sc0 - m);
        const float e1 = __expf(sc1 - m);
        const float e2 = v2 ? __expf(sc2 - m) : 0.f;
        float lsum = e0 + e1 + e2;
#pragma unroll
        for (int off = 16; off > 0; off >>= 1)
            lsum += __shfl_xor_sync(0xffffffffu, lsum, off);
        const float invT = 1.f / lsum;
        Psh[warp][lane] = e0;
        Psh[warp][lane + 32] = e1;
        if (v2) Psh[warp][lane + 64] = e2;
        __syncwarp();

        float pi[4], pl[4];
        {
            float si[4], sl[4];
#pragma unroll
            for (int kk = 0; kk < 4; kk++) { si[kk] = 0.f; sl[kk] = 0.f; }
#pragma unroll
            for (int kk = 0; kk < 4; kk++) {
                const float* kp = &Ksh[(LTXT + kk) * KPAD];
                const float* lp = &Ksh[(LTXT + 4 + kk) * KPAD];
#pragma unroll
                for (int d = 0; d < D_; d++) {
                    si[kk] = fmaf(qv[d], kp[d], si[kk]);
                    sl[kk] = fmaf(qv[d], lp[d], sl[kk]);
                }
            }
            float mi = -1e30f, ml = -1e30f;
#pragma unroll
            for (int kk = 0; kk < 4; kk++) {
                si[kk] *= scale; sl[kk] *= scale;
                mi = fmaxf(mi, si[kk]); ml = fmaxf(ml, sl[kk]);
            }
            float sumi = 0.f, suml = 0.f;
#pragma unroll
            for (int kk = 0; kk < 4; kk++) {
                pi[kk] = __expf(si[kk] - mi); pl[kk] = __expf(sl[kk] - ml);
                sumi += pi[kk]; suml += pl[kk];
            }
            const float ri = 1.f / sumi, rl = 1.f / suml;
#pragma unroll
            for (int kk = 0; kk < 4; kk++) { pi[kk] *= ri; pl[kk] *= rl; }
        }

        float o0 = 0.f, o1 = 0.f;
        for (int k2 = 0; k2 < LTXT; k2++) {
            const float p = Psh[warp][k2];
            o0 = fmaf(p, Vsh[k2 * KPAD + lane], o0);
            o1 = fmaf(p, Vsh[k2 * KPAD + lane + 32], o1);
        }
        o0 *= invT; o1 *= invT;
#pragma unroll
        for (int kk = 0; kk < 4; kk++) {
            o0 = fmaf(pi[kk], Vsh[(LTXT + kk) * KPAD + lane], o0);
            o1 = fmaf(pi[kk], Vsh[(LTXT + kk) * KPAD + lane + 32], o1);
            o0 = fmaf(pl[kk], Vsh[(LTXT + 4 + kk) * KPAD + lane], o0);
            o1 = fmaf(pl[kk], Vsh[(LTXT + 4 + kk) * KPAD + lane + 32], o1);
        }
        const long long base = ((long long)b * S_ + s) * C_ + h * D_;
        const __nv_bfloat16 h0 = __float2bfloat16(o0);
        const __nv_bfloat16 h1 = __float2bfloat16(o1);
        ohi[base + lane]      = h0;
        ohi[base + lane + 32] = h1;
        olo[base + lane]      = __float2bfloat16(o0 - __bfloat162float(h0));
        olo[base + lane + 32] = __float2bfloat16(o1 - __bfloat162float(h1));
        __syncwarp();
    }
}

// ---------------------------------------------------------------------------
// Launch
// ---------------------------------------------------------------------------
extern "C" void kernel_launch(void* const* d_in, const int* in_sizes, int n_in,
                              void* d_out, int out_size) {
    const float* hidden = (const float*)d_in[0];
    const float* enc    = (const float*)d_in[1];
    const float* Wq     = (const float*)d_in[2];
    const float* Wk     = (const float*)d_in[3];
    const float* Wv     = (const float*)d_in[4];
    const float* Wk_ip  = (const float*)d_in[5];
    const float* Wv_ip  = (const float*)d_in[6];
    const float* Wk_lbl = (const float*)d_in[7];
    const float* Wv_lbl = (const float*)d_in[8];
    const float* Wo     = (const float*)d_in[9];
    const float* bo     = (const float*)d_in[10];
    float* out = (float*)d_out;

    float *qb, *kb, *vb;
    __nv_bfloat16 *ahi, *alo, *wqhi, *wqlo, *wohi, *wolo;
    cudaGetSymbolAddress((void**)&qb, g_q);
    cudaGetSymbolAddress((void**)&kb, g_k);
    cudaGetSymbolAddress((void**)&vb, g_v);
    cudaGetSymbolAddress((void**)&ahi, g_ahi);
    cudaGetSymbolAddress((void**)&alo, g_alo);
    cudaGetSymbolAddress((void**)&wqhi, g_wqhi);
    cudaGetSymbolAddress((void**)&wqlo, g_wqlo);
    cudaGetSymbolAddress((void**)&wohi, g_wohi);
    cudaGetSymbolAddress((void**)&wolo, g_wolo);

    cudaFuncSetAttribute(gemm_mma, cudaFuncAttributeMaxDynamicSharedMemorySize,
                         SMEM_GEMM);

    // 1. Convert hidden + weights to bf16 hi/lo (weights transposed to [N,K])
    {
        const long long n4 = (long long)MTOT * C_ / 4;
        conv_split<<<(unsigned)((n4 + 255) / 256), 256>>>(hidden, ahi, alo, n4);
        dim3 gw(C_ / 32, C_ / 32), bw(32, 8);
        conv_w_t<<<gw, bw>>>(Wq, wqhi, wqlo);
        conv_w_t<<<gw, bw>>>(Wo, wohi, wolo);
    }

    // 2. Q projection (tensor cores): g_q = hidden @ Wq
    gemm_mma<<<dim3(C_ / 128, MTOT / 128), 256, SMEM_GEMM>>>(
        ahi, alo, wqhi, wqlo, qb, nullptr, nullptr);

    // 3. KV projections (split-K + atomics)
    {
        cudaMemsetAsync(kb, 0, (size_t)B_ * LTOT * C_ * sizeof(float));
        cudaMemsetAsync(vb, 0, (size_t)B_ * LTOT * C_ * sizeof(float));
        const long long sA = (long long)LTOT * DC_;
        const long long sC = (long long)LTOT * C_;
        dim3 blk(256);
        dim3 gT(C_ / 64, 3 * KSPLIT, B_);
        dim3 gS(C_ / 64, 1 * KSPLIT, B_);
        sgemm32s<<<gT, blk>>>(enc, Wk, kb, LTXT, sA, sC);
        sgemm32s<<<gT, blk>>>(enc, Wv, vb, LTXT, sA, sC);
        sgemm32s<<<gS, blk>>>(enc + (long long)LTXT * DC_, Wk_ip,
                              kb + (long long)LTXT * C_, LIMG, sA, sC);
        sgemm32s<<<gS, blk>>>(enc + (long long)LTXT * DC_, Wv_ip,
                              vb + (long long)LTXT * C_, LIMG, sA, sC);
        sgemm32s<<<gS, blk>>>(enc + (long long)(LTXT + LIMG) * DC_, Wk_lbl,
                              kb + (long long)(LTXT + LIMG) * C_, LLBL, sA, sC);
        sgemm32s<<<gS, blk>>>(enc + (long long)(LTXT + LIMG) * DC_, Wv_lbl,
                              vb + (long long)(LTXT + LIMG) * C_, LLBL, sA, sC);
    }

    // 4. Attention -> bf16 hi/lo activation scratch
    attn_kernel<<<dim3(B_ * H_, 8), 256>>>(qb, kb, vb, ahi, alo);

    // 5. Output projection + bias + residual (tensor cores)
    gemm_mma<<<dim3(C_ / 128, MTOT / 128), 256, SMEM_GEMM>>>(
        ahi, alo, wohi, wolo, out, bo, hidden);
}

// round 6
// speedup vs baseline: 2.2936x; 1.3234x over previous
#include <cuda_runtime.h>
#include <cuda_bf16.h>
#include <cstdint>

// Problem dims
#define B_   4
#define S_   4096
#define C_   1280
#define DC_  2048
#define H_   20
#define D_   64
#define LTXT 77
#define LIMG 4
#define LLBL 4
#define LTOT 85
#define KPAD 68    // floats per K/V smem row: mult of 4 (float4 aligned), conflict-free
#define MTOT (B_ * S_)   // 16384

// ---------------------------------------------------------------------------
// Device scratch
// ---------------------------------------------------------------------------
__device__ float g_q[(size_t)MTOT * C_];                    // fp32 Q for attention
__device__ __nv_bfloat16 g_ahi[(size_t)MTOT * C_];          // activation hi
__device__ __nv_bfloat16 g_alo[(size_t)MTOT * C_];          // activation lo
__device__ __nv_bfloat16 g_wqhi[(size_t)C_ * C_];           // Wq^T hi  [N,K]
__device__ __nv_bfloat16 g_wqlo[(size_t)C_ * C_];
__device__ __nv_bfloat16 g_wohi[(size_t)C_ * C_];           // Wo^T hi
__device__ __nv_bfloat16 g_wolo[(size_t)C_ * C_];
__device__ float g_k[(size_t)B_ * LTOT * C_];
__device__ float g_v[(size_t)B_ * LTOT * C_];

// ---------------------------------------------------------------------------
// small PTX helpers (stable ISA: ldmatrix / mma.sync / cp.async)
// ---------------------------------------------------------------------------
__device__ __forceinline__ uint32_t smem_u32(const void* p) {
    uint32_t a;
    asm("{ .reg .u64 t; cvta.to.shared.u64 t, %1; cvt.u32.u64 %0, t; }"
        : "=r"(a) : "l"(p));
    return a;
}

__device__ __forceinline__ void cp_async16(uint32_t dst, const void* src) {
    asm volatile("cp.async.cg.shared.global [%0], [%1], 16;"
                 :: "r"(dst), "l"(src));
}
__device__ __forceinline__ void cp_commit() {
    asm volatile("cp.async.commit_group;");
}
__device__ __forceinline__ void cp_wait2() {
    asm volatile("cp.async.wait_group 2;");
}

__device__ __forceinline__ void ldsm_x4(uint32_t* r, uint32_t addr) {
    asm volatile("ldmatrix.sync.aligned.m8n8.x4.shared.b16 {%0,%1,%2,%3}, [%4];"
                 : "=r"(r[0]), "=r"(r[1]), "=r"(r[2]), "=r"(r[3]) : "r"(addr));
}
__device__ __forceinline__ void ldsm_x2(uint32_t* r, uint32_t addr) {
    asm volatile("ldmatrix.sync.aligned.m8n8.x2.shared.b16 {%0,%1}, [%2];"
                 : "=r"(r[0]), "=r"(r[1]) : "r"(addr));
}

__device__ __forceinline__ void mma_bf16(float* c, const uint32_t* a,
                                         const uint32_t* b) {
    asm volatile(
        "mma.sync.aligned.m16n8k16.row.col.f32.bf16.bf16.f32 "
        "{%0,%1,%2,%3}, {%4,%5,%6,%7}, {%8,%9}, {%0,%1,%2,%3};"
        : "+f"(c[0]), "+f"(c[1]), "+f"(c[2]), "+f"(c[3])
        : "r"(a[0]), "r"(a[1]), "r"(a[2]), "r"(a[3]), "r"(b[0]), "r"(b[1]));
}

// ---------------------------------------------------------------------------
// Conversion kernels
// ---------------------------------------------------------------------------
__global__ void conv_split(const float* __restrict__ src,
                           __nv_bfloat16* __restrict__ hi,
                           __nv_bfloat16* __restrict__ lo, long long n4) {
    long long i = (long long)blockIdx.x * blockDim.x + threadIdx.x;
    if (i >= n4) return;
    float4 v = ((const float4*)src)[i];
    __nv_bfloat16 h[4], l[4];
    float f[4] = {v.x, v.y, v.z, v.w};
#pragma unroll
    for (int j = 0; j < 4; j++) {
        h[j] = __float2bfloat16(f[j]);
        l[j] = __float2bfloat16(f[j] - __bfloat162float(h[j]));
    }
    ((uint2*)hi)[i] = *(uint2*)h;
    ((uint2*)lo)[i] = *(uint2*)l;
}

// W (K x N fp32, row-major) -> Wt hi/lo (N x K bf16, K contiguous)
__global__ void conv_w_t(const float* __restrict__ W,
                         __nv_bfloat16* __restrict__ Thi,
                         __nv_bfloat16* __restrict__ Tlo) {
    __shared__ float t[32][33];
    const int n0 = blockIdx.x * 32, k0 = blockIdx.y * 32;
    const int tx = threadIdx.x, ty = threadIdx.y;  // 32 x 8
#pragma unroll
    for (int i = 0; i < 4; i++) {
        const int kk = ty + 8 * i;
        t[kk][tx] = W[(long long)(k0 + kk) * C_ + n0 + tx];
    }
    __syncthreads();
#pragma unroll
    for (int i = 0; i < 4; i++) {
        const int nn = ty + 8 * i;
        const float v = t[tx][nn];
        const __nv_bfloat16 h = __float2bfloat16(v);
        const long long o = (long long)(n0 + nn) * C_ + k0 + tx;
        Thi[o] = h;
        Tlo[o] = __float2bfloat16(v - __bfloat162float(h));
    }
}

// ---------------------------------------------------------------------------
// bf16 split-precision GEMM via mma.sync (HMMA), fp32 accumulate.
// D[M,N] = (Ahi+Alo)[M,K] @ (Bhi+Blo)^T[N,K]  (3 products)
// CTA 128x128, BK=32, 8 warps (warp tile 64x32), padded smem rows (40 bf16),
// 4-stage cp.async pipeline (wait_group 2). Grid (N/128, M/128).
// ---------------------------------------------------------------------------
#define GK    C_            // 1280
#define NIT   (GK / 32)     // 40
#define ROWB  40            // bf16 elems per smem row (32 + 8 pad) -> 80 bytes
#define TILEB (128 * ROWB * 2)          // 10240 bytes per tile
#define STAGEB (4 * TILEB)              // Ahi, Alo, Bhi, Blo = 40960
#define NSTAGE 4
#define SMEM_GEMM (NSTAGE * STAGEB)     // 163840 bytes

__device__ __forceinline__ void gemm_issue_stage(
    uint32_t sbase, const __nv_bfloat16* Ahi, const __nv_bfloat16* Alo,
    const __nv_bfloat16* Bhi, const __nv_bfloat16* Blo,
    int bm, int bn, int k0, int tid)
{
    const __nv_bfloat16* srcs[4] = {Ahi + (long long)bm * GK,
                                    Alo + (long long)bm * GK,
                                    Bhi + (long long)bn * GK,
                                    Blo + (long long)bn * GK};
#pragma unroll
    for (int t = 0; t < 4; t++) {
#pragma unroll
        for (int i = 0; i < 2; i++) {
            const int c   = tid + 256 * i;       // 0..511
            const int row = c >> 2;
            const int ch  = c & 3;
            const void* src = srcs[t] + (long long)row * GK + k0 + ch * 8;
            cp_async16(sbase + t * TILEB + row * (ROWB * 2) + ch * 16, src);
        }
    }
    cp_commit();
}

__global__ __launch_bounds__(256, 1)
void gemm_mma(const __nv_bfloat16* __restrict__ Ahi,
              const __nv_bfloat16* __restrict__ Alo,
              const __nv_bfloat16* __restrict__ Bhi,
              const __nv_bfloat16* __restrict__ Blo,
              float* __restrict__ Cout,
              const float* __restrict__ bias,
              const float* __restrict__ resid)
{
    extern __shared__ char smem[];
    const int tid  = threadIdx.x;
    const int warp = tid >> 5;
    const int lane = tid & 31;
    const int bm   = blockIdx.y * 128;
    const int bn   = blockIdx.x * 128;
    const uint32_t sb = smem_u32(smem);

    const int wm = (warp >> 2) * 64;   // warp M offset (0 or 64)
    const int wn = (warp & 3) * 32;    // warp N offset (0,32,64,96)

    float acc[4][4][4];
#pragma unroll
    for (int i = 0; i < 4; i++)
#pragma unroll
        for (int j = 0; j < 4; j++)
#pragma unroll
            for (int e = 0; e < 4; e++) acc[i][j][e] = 0.f;

    const int lmat = lane >> 3;
    const int lrow = lane & 7;
    const int aRow  = (lmat & 1) * 8 + lrow;
    const int aKoff = (lmat >> 1) * 8;
    const int bmat  = lmat & 1;
    const int bRow  = lrow;

    // prologue: 3 stages in flight
    gemm_issue_stage(sb + 0 * STAGEB, Ahi, Alo, Bhi, Blo, bm, bn, 0, tid);
    gemm_issue_stage(sb + 1 * STAGEB, Ahi, Alo, Bhi, Blo, bm, bn, 32, tid);
    gemm_issue_stage(sb + 2 * STAGEB, Ahi, Alo, Bhi, Blo, bm, bn, 64, tid);

    for (int it = 0; it < NIT; it++) {
        cp_wait2();          // stage `it` complete (3 groups in flight -> wait oldest)
        __syncthreads();     // everyone done reading stage (it-1) last iter
        if (it + 3 < NIT)
            gemm_issue_stage(sb + ((it + 3) & (NSTAGE - 1)) * STAGEB,
                             Ahi, Alo, Bhi, Blo, bm, bn, (it + 3) * 32, tid);
        else
            cp_commit();     // empty group keeps wait_group count calibrated

        const uint32_t st = sb + (it & (NSTAGE - 1)) * STAGEB;
        const uint32_t sAh = st, sAl = st + TILEB;
        const uint32_t sBh = st + 2 * TILEB, sBl = st + 3 * TILEB;

#pragma unroll
        for (int ks = 0; ks < 2; ks++) {
            uint32_t ah[4][4], al[4][4], bh[4][2], bl[4][2];
#pragma unroll
            for (int i = 0; i < 4; i++) {
                const uint32_t off =
                    (uint32_t)(wm + i * 16 + aRow) * (ROWB * 2) +
                    (uint32_t)(ks * 16 + aKoff) * 2;
                ldsm_x4(ah[i], sAh + off);
                ldsm_x4(al[i], sAl + off);
            }
#pragma unroll
            for (int j = 0; j < 4; j++) {
                const uint32_t off =
                    (uint32_t)(wn + j * 8 + bRow) * (ROWB * 2) +
                    (uint32_t)(ks * 16 + bmat * 8) * 2;
                ldsm_x2(bh[j], sBh + off);
                ldsm_x2(bl[j], sBl + off);
            }
#pragma unroll
            for (int i = 0; i < 4; i++)
#pragma unroll
                for (int j = 0; j < 4; j++) {
                    mma_bf16(acc[i][j], ah[i], bh[j]);
                    mma_bf16(acc[i][j], ah[i], bl[j]);
                    mma_bf16(acc[i][j], al[i], bh[j]);
                }
        }
    }

    // epilogue: acc -> gmem fp32 (+bias)(+resid)
#pragma unroll
    for (int i = 0; i < 4; i++) {
#pragma unroll
        for (int j = 0; j < 4; j++) {
            const int col = bn + wn + j * 8 + (lane & 3) * 2;
#pragma unroll
            for (int half = 0; half < 2; half++) {
                const long long row = bm + wm + i * 16 + (lane >> 2) + half * 8;
                float2 o;
                o.x = acc[i][j][half * 2 + 0];
                o.y = acc[i][j][half * 2 + 1];
                if (bias) { o.x += bias[col]; o.y += bias[col + 1]; }
                if (resid) {
                    const float2 rv = *(const float2*)(resid + row * C_ + col);
                    o.x += rv.x; o.y += rv.y;
                }
                *(float2*)(Cout + row * C_ + col) = o;
            }
        }
    }
}

// ---------------------------------------------------------------------------
// Split-K thin GEMM for the KV projections (atomicAdd into zeroed output).
// ---------------------------------------------------------------------------
#define KSPLIT 8
#define KCHUNK (DC_ / KSPLIT)

__global__ __launch_bounds__(256)
void sgemm32s(const float* __restrict__ Abase,
              const float* __restrict__ Bw,
              float* __restrict__ Cbase,
              int M, long long strideA, long long strideC) {
    __shared__ float As[32][33];
    __shared__ float Bs[32][64];

    const float* A = Abase + (long long)blockIdx.z * strideA;
    float*       Cc = Cbase + (long long)blockIdx.z * strideC;

    const int rt = blockIdx.y / KSPLIT;
    const int ks = blockIdx.y % KSPLIT;
    const int bm = rt * 32;
    const int bn = blockIdx.x * 64;
    const int kc0 = ks * KCHUNK;

    const int tid = threadIdx.x;
    const int tx = tid & 15, ty = tid >> 4;
    const int aRow = tid >> 3, aCol = (tid & 7) << 2;
    const int bRow = tid >> 4, bCol = (tid & 15) << 2;

    float acc[2][4];
#pragma unroll
    for (int i = 0; i < 2; i++)
#pragma unroll
        for (int j = 0; j < 4; j++) acc[i][j] = 0.f;

    for (int k0 = kc0; k0 < kc0 + KCHUNK; k0 += 32) {
        float4 av = make_float4(0.f, 0.f, 0.f, 0.f);
        if (bm + aRow < M)
            av = *(const float4*)(A + (long long)(bm + aRow) * DC_ + k0 + aCol);
        As[aCol + 0][aRow] = av.x;
        As[aCol + 1][aRow] = av.y;
        As[aCol + 2][aRow] = av.z;
        As[aCol + 3][aRow] = av.w;
#pragma unroll
        for (int p = 0; p < 2; p++) {
            const int r = bRow + p * 16;
            *(float4*)&Bs[r][bCol] =
                *(const float4*)(Bw + (long long)(k0 + r) * C_ + bn + bCol);
        }
        __syncthreads();
#pragma unroll
        for (int kk = 0; kk < 32; kk++) {
            const float a0 = As[kk][ty * 2];
            const float a1 = As[kk][ty * 2 + 1];
            const float4 b = *(const float4*)&Bs[kk][tx * 4];
            acc[0][0] = fmaf(a0, b.x, acc[0][0]);
            acc[0][1] = fmaf(a0, b.y, acc[0][1]);
            acc[0][2] = fmaf(a0, b.z, acc[0][2]);
            acc[0][3] = fmaf(a0, b.w, acc[0][3]);
            acc[1][0] = fmaf(a1, b.x, acc[1][0]);
            acc[1][1] = fmaf(a1, b.y, acc[1][1]);
            acc[1][2] = fmaf(a1, b.z, acc[1][2]);
            acc[1][3] = fmaf(a1, b.w, acc[1][3]);
        }
        __syncthreads();
    }

#pragma unroll
    for (int i = 0; i < 2; i++) {
        const int r = bm + ty * 2 + i;
        if (r < M) {
            float* cp = Cc + (long long)r * C_ + bn + tx * 4;
#pragma unroll
            for (int j = 0; j < 4; j++) atomicAdd(cp + j, acc[i][j]);
        }
    }
}

// ---------------------------------------------------------------------------
// Fused 3-branch cross-attention, v2.
// All 85 keys distributed over lanes in 3 score slots:
//   slot0: key = lane (0..31); slot1: key = lane+32 (32..63)
//   slot2: lanes 0..12 -> text keys 64..76; lanes 24..27 -> img 77..80;
//          lanes 28..31 -> lbl 81..84 (softmax per 4-lane group via xor-1/2)
// 2 queries per warp per iteration; float4 smem loads (KPAD=68).
// Writes bf16 hi/lo for the O-projection.
// ---------------------------------------------------------------------------
#define ATTN_SMEM ((2 * LTOT * KPAD + 8 * 2 * 88) * 4)

__global__ __launch_bounds__(256, 2)
void attn_kernel(const float* __restrict__ q,
                 const float* __restrict__ kall,
                 const float* __restrict__ vall,
                 __nv_bfloat16* __restrict__ ohi,
                 __nv_bfloat16* __restrict__ olo) {
    extern __shared__ float sm[];
    float* Ksh = sm;                       // LTOT*KPAD
    float* Vsh = sm + LTOT * KPAD;
    float* Pall = sm + 2 * LTOT * KPAD;    // [8][2][88]

    const int bh = blockIdx.x;
    const int b = bh / H_, h = bh % H_;
    const int tid = threadIdx.x, lane = tid & 31, warp = tid >> 5;

    for (int i = tid; i < LTOT * D_; i += 256) {
        const int l = i >> 6, d = i & 63;
        const long long g = ((long long)b * LTOT + l) * C_ + h * D_ + d;
        Ksh[l * KPAD + d] = kall[g];
        Vsh[l * KPAD + d] = vall[g];
    }
    __syncthreads();

    const int sPer = S_ / gridDim.y;
    const int s0 = blockIdx.y * sPer;
    const float scale = 0.125f;

    const int k2 = (lane < 13) ? (64 + lane) : ((lane >= 24) ? (53 + lane) : 0);
    const float* K0 = Ksh + lane * KPAD;
    const float* K1 = Ksh + (lane + 32) * KPAD;
    const float* K2 = Ksh + k2 * KPAD;
    float* Pa = Pall + (warp * 2 + 0) * 88;
    float* Pb = Pall + (warp * 2 + 1) * 88;

    for (int s = s0 + warp * 2; s < s0 + sPer; s += 16) {
        const float* qpa = q + ((long long)b * S_ + s) * C_ + h * D_;
        const float* qpb = qpa + C_;

        float s0a = 0.f, s1a = 0.f, s2a = 0.f;
        float s0b = 0.f, s1b = 0.f, s2b = 0.f;
#pragma unroll
        for (int half = 0; half < 2; half++) {
            float4 qa4[8], qb4[8];
#pragma unroll
            for (int i = 0; i < 8; i++) {
                qa4[i] = *(const float4*)(qpa + half * 32 + i * 4);
                qb4[i] = *(const float4*)(qpb + half * 32 + i * 4);
            }
#pragma unroll
            for (int i = 0; i < 8; i++) {
                const int d = half * 32 + i * 4;
                const float4 v0 = *(const float4*)(K0 + d);
                const float4 v1 = *(const float4*)(K1 + d);
                const float4 v2 = *(const float4*)(K2 + d);
                s0a = fmaf(qa4[i].x, v0.x, s0a); s0a = fmaf(qa4[i].y, v0.y, s0a);
                s0a = fmaf(qa4[i].z, v0.z, s0a); s0a = fmaf(qa4[i].w, v0.w, s0a);
                s1a = fmaf(qa4[i].x, v1.x, s1a); s1a = fmaf(qa4[i].y, v1.y, s1a);
                s1a = fmaf(qa4[i].z, v1.z, s1a); s1a = fmaf(qa4[i].w, v1.w, s1a);
                s2a = fmaf(qa4[i].x, v2.x, s2a); s2a = fmaf(qa4[i].y, v2.y, s2a);
                s2a = fmaf(qa4[i].z, v2.z, s2a); s2a = fmaf(qa4[i].w, v2.w, s2a);
                s0b = fmaf(qb4[i].x, v0.x, s0b); s0b = fmaf(qb4[i].y, v0.y, s0b);
                s0b = fmaf(qb4[i].z, v0.z, s0b); s0b = fmaf(qb4[i].w, v0.w, s0b);
                s1b = fmaf(qb4[i].x, v1.x, s1b); s1b = fmaf(qb4[i].y, v1.y, s1b);
                s1b = fmaf(qb4[i].z, v1.z, s1b); s1b = fmaf(qb4[i].w, v1.w, s1b);
                s2b = fmaf(qb4[i].x, v2.x, s2b); s2b = fmaf(qb4[i].y, v2.y, s2b);
                s2b = fmaf(qb4[i].z, v2.z, s2b); s2b = fmaf(qb4[i].w, v2.w, s2b);
            }
        }
        s0a *= scale; s1a *= scale; s2a *= scale;
        s0b *= scale; s1b *= scale; s2b *= scale;

        // ---- text softmax (keys 0..76) ----
        const bool isTxt2 = (lane < 13);
        float ma = fmaxf(s0a, s1a); if (isTxt2) ma = fmaxf(ma, s2a);
        float mb = fmaxf(s0b, s1b); if (isTxt2) mb = fmaxf(mb, s2b);
#pragma unroll
        for (int off = 16; off > 0; off >>= 1) {
            ma = fmaxf(ma, __shfl_xor_sync(0xffffffffu, ma, off));
            mb = fmaxf(mb, __shfl_xor_sync(0xffffffffu, mb, off));
        }
        const float e0a = __expf(s0a - ma), e1a = __expf(s1a - ma);
        const float e2a = isTxt2 ? __expf(s2a - ma) : 0.f;
        const float e0b = __expf(s0b - mb), e1b = __expf(s1b - mb);
        const float e2b = isTxt2 ? __expf(s2b - mb) : 0.f;
        float ta = e0a + e1a + e2a, tb = e0b + e1b + e2b;
#pragma unroll
        for (int off = 16; off > 0; off >>= 1) {
            ta += __shfl_xor_sync(0xffffffffu, ta, off);
            tb += __shfl_xor_sync(0xffffffffu, tb, off);
        }
        const float ia = 1.f / ta, ib = 1.f / tb;

        // ---- img/lbl softmax: aligned 4-lane groups (24..27, 28..31) ----
        float ga = s2a, gb = s2b;
        ga = fmaxf(ga, __shfl_xor_sync(0xffffffffu, ga, 1));
        ga = fmaxf(ga, __shfl_xor_sync(0xffffffffu, ga, 2));
        gb = fmaxf(gb, __shfl_xor_sync(0xffffffffu, gb, 1));
        gb = fmaxf(gb, __shfl_xor_sync(0xffffffffu, gb, 2));
        const float ega = __expf(s2a - ga), egb = __expf(s2b - gb);
        float gsa = ega, gsb = egb;
        gsa += __shfl_xor_sync(0xffffffffu, gsa, 1);
        gsa += __shfl_xor_sync(0xffffffffu, gsa, 2);
        gsb += __shfl_xor_sync(0xffffffffu, gsb, 1);
        gsb += __shfl_xor_sync(0xffffffffu, gsb, 2);
        const float pga = ega / gsa, pgb = egb / gsb;

        Pa[lane] = e0a * ia;      Pb[lane] = e0b * ib;
        Pa[lane + 32] = e1a * ia; Pb[lane + 32] = e1b * ib;
        if (isTxt2) { Pa[lane + 64] = e2a * ia; Pb[lane + 64] = e2b * ib; }
        if (lane >= 24) { Pa[lane + 53] = pga; Pb[lane + 53] = pgb; }
        __syncwarp();

        // ---- output: lane owns dims (lane, lane+32) for both queries ----
        float o0a = 0.f, o1a = 0.f, o0b = 0.f, o1b = 0.f;
#pragma unroll 5
        for (int k = 0; k < LTOT; k++) {
            const float v0 = Vsh[k * KPAD + lane];
            const float v1 = Vsh[k * KPAD + lane + 32];
            const float pa = Pa[k], pb = Pb[k];
            o0a = fmaf(pa, v0, o0a); o1a = fmaf(pa, v1, o1a);
            o0b = fmaf(pb, v0, o0b); o1b = fmaf(pb, v1, o1b);
        }

        const long long basea = ((long long)b * S_ + s) * C_ + h * D_;
        const long long baseb = basea + C_;
        const __nv_bfloat16 h0a = __float2bfloat16(o0a);
        const __nv_bfloat16 h1a = __float2bfloat16(o1a);
        const __nv_bfloat16 h0b = __float2bfloat16(o0b);
        const __nv_bfloat16 h1b = __float2bfloat16(o1b);
        ohi[basea + lane]      = h0a;
        ohi[basea + lane + 32] = h1a;
        ohi[baseb + lane]      = h0b;
        ohi[baseb + lane + 32] = h1b;
        olo[basea + lane]      = __float2bfloat16(o0a - __bfloat162float(h0a));
        olo[basea + lane + 32] = __float2bfloat16(o1a - __bfloat162float(h1a));
        olo[baseb + lane]      = __float2bfloat16(o0b - __bfloat162float(h0b));
        olo[baseb + lane + 32] = __float2bfloat16(o1b - __bfloat162float(h1b));
        __syncwarp();
    }
}

// ---------------------------------------------------------------------------
// Launch
// ---------------------------------------------------------------------------
extern "C" void kernel_launch(void* const* d_in, const int* in_sizes, int n_in,
                              void* d_out, int out_size) {
    const float* hidden = (const float*)d_in[0];
    const float* enc    = (const float*)d_in[1];
    const float* Wq     = (const float*)d_in[2];
    const float* Wk     = (const float*)d_in[3];
    const float* Wv     = (const float*)d_in[4];
    const float* Wk_ip  = (const float*)d_in[5];
    const float* Wv_ip  = (const float*)d_in[6];
    const float* Wk_lbl = (const float*)d_in[7];
    const float* Wv_lbl = (const float*)d_in[8];
    const float* Wo     = (const float*)d_in[9];
    const float* bo     = (const float*)d_in[10];
    float* out = (float*)d_out;

    float *qb, *kb, *vb;
    __nv_bfloat16 *ahi, *alo, *wqhi, *wqlo, *wohi, *wolo;
    cudaGetSymbolAddress((void**)&qb, g_q);
    cudaGetSymbolAddress((void**)&kb, g_k);
    cudaGetSymbolAddress((void**)&vb, g_v);
    cudaGetSymbolAddress((void**)&ahi, g_ahi);
    cudaGetSymbolAddress((void**)&alo, g_alo);
    cudaGetSymbolAddress((void**)&wqhi, g_wqhi);
    cudaGetSymbolAddress((void**)&wqlo, g_wqlo);
    cudaGetSymbolAddress((void**)&wohi, g_wohi);
    cudaGetSymbolAddress((void**)&wolo, g_wolo);

    cudaFuncSetAttribute(gemm_mma, cudaFuncAttributeMaxDynamicSharedMemorySize,
                         SMEM_GEMM);
    cudaFuncSetAttribute(attn_kernel, cudaFuncAttributeMaxDynamicSharedMemorySize,
                         ATTN_SMEM);

    // 1. Convert hidden + weights to bf16 hi/lo (weights transposed to [N,K])
    {
        const long long n4 = (long long)MTOT * C_ / 4;
        conv_split<<<(unsigned)((n4 + 255) / 256), 256>>>(hidden, ahi, alo, n4);
        dim3 gw(C_ / 32, C_ / 32), bw(32, 8);
        conv_w_t<<<gw, bw>>>(Wq, wqhi, wqlo);
        conv_w_t<<<gw, bw>>>(Wo, wohi, wolo);
    }

    // 2. Q projection (tensor cores): g_q = hidden @ Wq
    gemm_mma<<<dim3(C_ / 128, MTOT / 128), 256, SMEM_GEMM>>>(
        ahi, alo, wqhi, wqlo, qb, nullptr, nullptr);

    // 3. KV projections (split-K + atomics)
    {
        cudaMemsetAsync(kb, 0, (size_t)B_ * LTOT * C_ * sizeof(float));
        cudaMemsetAsync(vb, 0, (size_t)B_ * LTOT * C_ * sizeof(float));
        const long long sA = (long long)LTOT * DC_;
        const long long sC = (long long)LTOT * C_;
        dim3 blk(256);
        dim3 gT(C_ / 64, 3 * KSPLIT, B_);
        dim3 gS(C_ / 64, 1 * KSPLIT, B_);
        sgemm32s<<<gT, blk>>>(enc, Wk, kb, LTXT, sA, sC);
        sgemm32s<<<gT, blk>>>(enc, Wv, vb, LTXT, sA, sC);
        sgemm32s<<<gS, blk>>>(enc + (long long)LTXT * DC_, Wk_ip,
                              kb + (long long)LTXT * C_, LIMG, sA, sC);
        sgemm32s<<<gS, blk>>>(enc + (long long)LTXT * DC_, Wv_ip,
                              vb + (long long)LTXT * C_, LIMG, sA, sC);
        sgemm32s<<<gS, blk>>>(enc + (long long)(LTXT + LIMG) * DC_, Wk_lbl,
                              kb + (long long)(LTXT + LIMG) * C_, LLBL, sA, sC);
        sgemm32s<<<gS, blk>>>(enc + (long long)(LTXT + LIMG) * DC_, Wv_lbl,
                              vb + (long long)(LTXT + LIMG) * C_, LLBL, sA, sC);
    }

    // 4. Attention -> bf16 hi/lo activation scratch
    attn_kernel<<<dim3(B_ * H_, 16), 256, ATTN_SMEM>>>(qb, kb, vb, ahi, alo);

    // 5. Output projection + bias + residual (tensor cores)
    gemm_mma<<<dim3(C_ / 128, MTOT / 128), 256, SMEM_GEMM>>>(
        ahi, alo, wohi, wolo, out, bo, hidden);
}

// round 7
// speedup vs baseline: 2.3059x; 1.0054x over previous
#include <cuda_runtime.h>
#include <cuda_bf16.h>
#include <cstdint>

// Problem dims
#define B_   4
#define S_   4096
#define C_   1280
#define DC_  2048
#define H_   20
#define D_   64
#define LTXT 77
#define LIMG 4
#define LLBL 4
#define LTOT 85
#define KPAD 68
#define MTOT (B_ * S_)   // 16384

// ---------------------------------------------------------------------------
// Device scratch
// ---------------------------------------------------------------------------
__device__ float g_q[(size_t)MTOT * C_];
__device__ __nv_bfloat16 g_ahi[(size_t)MTOT * C_];
__device__ __nv_bfloat16 g_alo[(size_t)MTOT * C_];
__device__ __nv_bfloat16 g_wqhi[(size_t)C_ * C_];
__device__ __nv_bfloat16 g_wqlo[(size_t)C_ * C_];
__device__ __nv_bfloat16 g_wohi[(size_t)C_ * C_];
__device__ __nv_bfloat16 g_wolo[(size_t)C_ * C_];
__device__ float g_k[(size_t)B_ * LTOT * C_];
__device__ float g_v[(size_t)B_ * LTOT * C_];

// ---------------------------------------------------------------------------
// PTX helpers (stable ISA)
// ---------------------------------------------------------------------------
__device__ __forceinline__ uint32_t smem_u32(const void* p) {
    uint32_t a;
    asm("{ .reg .u64 t; cvta.to.shared.u64 t, %1; cvt.u32.u64 %0, t; }"
        : "=r"(a) : "l"(p));
    return a;
}
__device__ __forceinline__ void cp_async16(uint32_t dst, const void* src) {
    asm volatile("cp.async.cg.shared.global [%0], [%1], 16;" :: "r"(dst), "l"(src));
}
__device__ __forceinline__ void cp_commit() {
    asm volatile("cp.async.commit_group;");
}
__device__ __forceinline__ void cp_wait1() {
    asm volatile("cp.async.wait_group 1;");
}
__device__ __forceinline__ void ldsm_x4(uint32_t* r, uint32_t addr) {
    asm volatile("ldmatrix.sync.aligned.m8n8.x4.shared.b16 {%0,%1,%2,%3}, [%4];"
                 : "=r"(r[0]), "=r"(r[1]), "=r"(r[2]), "=r"(r[3]) : "r"(addr));
}
__device__ __forceinline__ void mma_bf16(float* c, const uint32_t* a,
                                         const uint32_t* b) {
    asm volatile(
        "mma.sync.aligned.m16n8k16.row.col.f32.bf16.bf16.f32 "
        "{%0,%1,%2,%3}, {%4,%5,%6,%7}, {%8,%9}, {%0,%1,%2,%3};"
        : "+f"(c[0]), "+f"(c[1]), "+f"(c[2]), "+f"(c[3])
        : "r"(a[0]), "r"(a[1]), "r"(a[2]), "r"(a[3]), "r"(b[0]), "r"(b[1]));
}

// ---------------------------------------------------------------------------
// Conversion kernels
// ---------------------------------------------------------------------------
__global__ void conv_split(const float* __restrict__ src,
                           __nv_bfloat16* __restrict__ hi,
                           __nv_bfloat16* __restrict__ lo, long long n4) {
    long long i = (long long)blockIdx.x * blockDim.x + threadIdx.x;
    if (i >= n4) return;
    float4 v = ((const float4*)src)[i];
    __nv_bfloat16 h[4], l[4];
    float f[4] = {v.x, v.y, v.z, v.w};
#pragma unroll
    for (int j = 0; j < 4; j++) {
        h[j] = __float2bfloat16(f[j]);
        l[j] = __float2bfloat16(f[j] - __bfloat162float(h[j]));
    }
    ((uint2*)hi)[i] = *(uint2*)h;
    ((uint2*)lo)[i] = *(uint2*)l;
}

__global__ void conv_w_t(const float* __restrict__ W,
                         __nv_bfloat16* __restrict__ Thi,
                         __nv_bfloat16* __restrict__ Tlo) {
    __shared__ float t[32][33];
    const int n0 = blockIdx.x * 32, k0 = blockIdx.y * 32;
    const int tx = threadIdx.x, ty = threadIdx.y;  // 32 x 8
#pragma unroll
    for (int i = 0; i < 4; i++) {
        const int kk = ty + 8 * i;
        t[kk][tx] = W[(long long)(k0 + kk) * C_ + n0 + tx];
    }
    __syncthreads();
#pragma unroll
    for (int i = 0; i < 4; i++) {
        const int nn = ty + 8 * i;
        const float v = t[tx][nn];
        const __nv_bfloat16 h = __float2bfloat16(v);
        const long long o = (long long)(n0 + nn) * C_ + k0 + tx;
        Thi[o] = h;
        Tlo[o] = __float2bfloat16(v - __bfloat162float(h));
    }
}

// ---------------------------------------------------------------------------
// bf16 split-precision GEMM v2 via mma.sync.
// CTA tile 128x256, 8 warps, warp tile 64x64. BK=32, 3-stage cp.async pipe.
// smem/stage: Ahi(128x32) Alo(128x32) Bhi(256x32) Blo(256x32), rows 40 bf16.
// ---------------------------------------------------------------------------
#define GK     C_            // 1280
#define NIT    (GK / 32)     // 40
#define ROWB   40            // bf16 per smem row (32 + 8 pad) = 80 B
#define TILEA  (128 * ROWB * 2)   // 10240
#define TILEBB (256 * ROWB * 2)   // 20480
#define OFF_AH 0
#define OFF_AL TILEA
#define OFF_BH (2 * TILEA)
#define OFF_BL (2 * TILEA + TILEBB)
#define STAGEB (2 * TILEA + 2 * TILEBB)   // 61440
#define NSTAGE 3
#define SMEM_GEMM (NSTAGE * STAGEB)       // 184320

__device__ __forceinline__ void gemm_issue_stage(
    uint32_t sbase, const __nv_bfloat16* Ahi, const __nv_bfloat16* Alo,
    const __nv_bfloat16* Bhi, const __nv_bfloat16* Blo,
    int bm, int bn, int k0, int tid)
{
    // A tiles: 128 rows -> 512 16B-chunks each
#pragma unroll
    for (int t = 0; t < 2; t++) {
        const __nv_bfloat16* src0 =
            (t == 0 ? Ahi : Alo) + (long long)bm * GK + k0;
#pragma unroll
        for (int i = 0; i < 2; i++) {
            const int c = tid + 256 * i;
            const int row = c >> 2, ch = c & 3;
            cp_async16(sbase + t * TILEA + row * 80 + ch * 16,
                       src0 + (long long)row * GK + ch * 8);
        }
    }
    // B tiles: 256 rows -> 1024 chunks each
#pragma unroll
    for (int t = 0; t < 2; t++) {
        const __nv_bfloat16* src0 =
            (t == 0 ? Bhi : Blo) + (long long)bn * GK + k0;
#pragma unroll
        for (int i = 0; i < 4; i++) {
            const int c = tid + 256 * i;
            const int row = c >> 2, ch = c & 3;
            cp_async16(sbase + OFF_BH + t * TILEBB + row * 80 + ch * 16,
                       src0 + (long long)row * GK + ch * 8);
        }
    }
    cp_commit();
}

__global__ __launch_bounds__(256, 1)
void gemm_mma(const __nv_bfloat16* __restrict__ Ahi,
              const __nv_bfloat16* __restrict__ Alo,
              const __nv_bfloat16* __restrict__ Bhi,
              const __nv_bfloat16* __restrict__ Blo,
              float* __restrict__ Cout,
              const float* __restrict__ bias,
              const float* __restrict__ resid)
{
    extern __shared__ char smem[];
    const int tid  = threadIdx.x;
    const int warp = tid >> 5;
    const int lane = tid & 31;
    const int bm   = blockIdx.y * 128;
    const int bn   = blockIdx.x * 256;
    const uint32_t sb = smem_u32(smem);

    const int wm = (warp >> 2) * 64;   // 0 or 64
    const int wn = (warp & 3) * 64;    // 0,64,128,192

    float acc[4][8][4];
#pragma unroll
    for (int i = 0; i < 4; i++)
#pragma unroll
        for (int j = 0; j < 8; j++)
#pragma unroll
            for (int e = 0; e < 4; e++) acc[i][j][e] = 0.f;

    const int lmat = lane >> 3;   // 0..3
    const int lrow = lane & 7;
    // A x4: row = wm + i*16 + (lmat&1)*8 + lrow, col = ks*16 + (lmat>>1)*8
    const int aRow  = (lmat & 1) * 8 + lrow;
    const int aKoff = (lmat >> 1) * 8;
    // B x4 (j-pair jp): row = wn + jp*16 + (lmat>>1)*8 + lrow, col = ks*16 + (lmat&1)*8
    const int bRow  = (lmat >> 1) * 8 + lrow;
    const int bKoff = (lmat & 1) * 8;

    gemm_issue_stage(sb + 0 * STAGEB, Ahi, Alo, Bhi, Blo, bm, bn, 0, tid);
    gemm_issue_stage(sb + 1 * STAGEB, Ahi, Alo, Bhi, Blo, bm, bn, 32, tid);

    int stage = 0;
    for (int it = 0; it < NIT; it++) {
        cp_wait1();
        __syncthreads();
        if (it + 2 < NIT) {
            int ns = stage + 2; if (ns >= NSTAGE) ns -= NSTAGE;
            gemm_issue_stage(sb + ns * STAGEB, Ahi, Alo, Bhi, Blo,
                             bm, bn, (it + 2) * 32, tid);
        } else {
            cp_commit();
        }

        const uint32_t st = sb + stage * STAGEB;

#pragma unroll
        for (int ks = 0; ks < 2; ks++) {
            uint32_t ah[4][4], al[4][4], bh[4][4], bl[4][4];
#pragma unroll
            for (int i = 0; i < 4; i++) {
                const uint32_t off =
                    (uint32_t)(wm + i * 16 + aRow) * 80 +
                    (uint32_t)(ks * 16 + aKoff) * 2;
                ldsm_x4(ah[i], st + OFF_AH + off);
                ldsm_x4(al[i], st + OFF_AL + off);
            }
#pragma unroll
            for (int jp = 0; jp < 4; jp++) {
                const uint32_t off =
                    (uint32_t)(wn + jp * 16 + bRow) * 80 +
                    (uint32_t)(ks * 16 + bKoff) * 2;
                ldsm_x4(bh[jp], st + OFF_BH + off);
                ldsm_x4(bl[jp], st + OFF_BL + off);
            }
#pragma unroll
            for (int i = 0; i < 4; i++)
#pragma unroll
                for (int jp = 0; jp < 4; jp++) {
                    mma_bf16(acc[i][2 * jp],     ah[i], &bh[jp][0]);
                    mma_bf16(acc[i][2 * jp],     ah[i], &bl[jp][0]);
                    mma_bf16(acc[i][2 * jp],     al[i], &bh[jp][0]);
                    mma_bf16(acc[i][2 * jp + 1], ah[i], &bh[jp][2]);
                    mma_bf16(acc[i][2 * jp + 1], ah[i], &bl[jp][2]);
                    mma_bf16(acc[i][2 * jp + 1], al[i], &bh[jp][2]);
                }
        }
        if (++stage == NSTAGE) stage = 0;
    }

    // epilogue
#pragma unroll
    for (int i = 0; i < 4; i++) {
#pragma unroll
        for (int j = 0; j < 8; j++) {
            const int col = bn + wn + j * 8 + (lane & 3) * 2;
#pragma unroll
            for (int half = 0; half < 2; half++) {
                const long long row = bm + wm + i * 16 + (lane >> 2) + half * 8;
                float2 o;
                o.x = acc[i][j][half * 2 + 0];
                o.y = acc[i][j][half * 2 + 1];
                if (bias) { o.x += bias[col]; o.y += bias[col + 1]; }
                if (resid) {
                    const float2 rv = *(const float2*)(resid + row * C_ + col);
                    o.x += rv.x; o.y += rv.y;
                }
                *(float2*)(Cout + row * C_ + col) = o;
            }
        }
    }
}

// ---------------------------------------------------------------------------
// Split-K thin GEMM for KV projections (atomicAdd into zeroed output).
// ---------------------------------------------------------------------------
#define KSPLIT 8
#define KCHUNK (DC_ / KSPLIT)

__global__ __launch_bounds__(256)
void sgemm32s(const float* __restrict__ Abase,
              const float* __restrict__ Bw,
              float* __restrict__ Cbase,
              int M, long long strideA, long long strideC) {
    __shared__ float As[32][33];
    __shared__ float Bs[32][64];

    const float* A = Abase + (long long)blockIdx.z * strideA;
    float*       Cc = Cbase + (long long)blockIdx.z * strideC;

    const int rt = blockIdx.y / KSPLIT;
    const int ks = blockIdx.y % KSPLIT;
    const int bm = rt * 32;
    const int bn = blockIdx.x * 64;
    const int kc0 = ks * KCHUNK;

    const int tid = threadIdx.x;
    const int tx = tid & 15, ty = tid >> 4;
    const int aRow = tid >> 3, aCol = (tid & 7) << 2;
    const int bRow = tid >> 4, bCol = (tid & 15) << 2;

    float acc[2][4];
#pragma unroll
    for (int i = 0; i < 2; i++)
#pragma unroll
        for (int j = 0; j < 4; j++) acc[i][j] = 0.f;

    for (int k0 = kc0; k0 < kc0 + KCHUNK; k0 += 32) {
        float4 av = make_float4(0.f, 0.f, 0.f, 0.f);
        if (bm + aRow < M)
            av = *(const float4*)(A + (long long)(bm + aRow) * DC_ + k0 + aCol);
        As[aCol + 0][aRow] = av.x;
        As[aCol + 1][aRow] = av.y;
        As[aCol + 2][aRow] = av.z;
        As[aCol + 3][aRow] = av.w;
#pragma unroll
        for (int p = 0; p < 2; p++) {
            const int r = bRow + p * 16;
            *(float4*)&Bs[r][bCol] =
                *(const float4*)(Bw + (long long)(k0 + r) * C_ + bn + bCol);
        }
        __syncthreads();
#pragma unroll
        for (int kk = 0; kk < 32; kk++) {
            const float a0 = As[kk][ty * 2];
            const float a1 = As[kk][ty * 2 + 1];
            const float4 b = *(const float4*)&Bs[kk][tx * 4];
            acc[0][0] = fmaf(a0, b.x, acc[0][0]);
            acc[0][1] = fmaf(a0, b.y, acc[0][1]);
            acc[0][2] = fmaf(a0, b.z, acc[0][2]);
            acc[0][3] = fmaf(a0, b.w, acc[0][3]);
            acc[1][0] = fmaf(a1, b.x, acc[1][0]);
            acc[1][1] = fmaf(a1, b.y, acc[1][1]);
            acc[1][2] = fmaf(a1, b.z, acc[1][2]);
            acc[1][3] = fmaf(a1, b.w, acc[1][3]);
        }
        __syncthreads();
    }

#pragma unroll
    for (int i = 0; i < 2; i++) {
        const int r = bm + ty * 2 + i;
        if (r < M) {
            float* cp = Cc + (long long)r * C_ + bn + tx * 4;
#pragma unroll
            for (int j = 0; j < 4; j++) atomicAdd(cp + j, acc[i][j]);
        }
    }
}

// ---------------------------------------------------------------------------
// Fused 3-branch cross-attention (round-6 version, unchanged).
// ---------------------------------------------------------------------------
#define ATTN_SMEM ((2 * LTOT * KPAD + 8 * 2 * 88) * 4)

__global__ __launch_bounds__(256, 2)
void attn_kernel(const float* __restrict__ q,
                 const float* __restrict__ kall,
                 const float* __restrict__ vall,
                 __nv_bfloat16* __restrict__ ohi,
                 __nv_bfloat16* __restrict__ olo) {
    extern __shared__ float sm[];
    float* Ksh = sm;
    float* Vsh = sm + LTOT * KPAD;
    float* Pall = sm + 2 * LTOT * KPAD;

    const int bh = blockIdx.x;
    const int b = bh / H_, h = bh % H_;
    const int tid = threadIdx.x, lane = tid & 31, warp = tid >> 5;

    for (int i = tid; i < LTOT * D_; i += 256) {
        const int l = i >> 6, d = i & 63;
        const long long g = ((long long)b * LTOT + l) * C_ + h * D_ + d;
        Ksh[l * KPAD + d] = kall[g];
        Vsh[l * KPAD + d] = vall[g];
    }
    __syncthreads();

    const int sPer = S_ / gridDim.y;
    const int s0 = blockIdx.y * sPer;
    const float scale = 0.125f;

    const int k2 = (lane < 13) ? (64 + lane) : ((lane >= 24) ? (53 + lane) : 0);
    const float* K0 = Ksh + lane * KPAD;
    const float* K1 = Ksh + (lane + 32) * KPAD;
    const float* K2 = Ksh + k2 * KPAD;
    float* Pa = Pall + (warp * 2 + 0) * 88;
    float* Pb = Pall + (warp * 2 + 1) * 88;

    for (int s = s0 + warp * 2; s < s0 + sPer; s += 16) {
        const float* qpa = q + ((long long)b * S_ + s) * C_ + h * D_;
        const float* qpb = qpa + C_;

        float s0a = 0.f, s1a = 0.f, s2a = 0.f;
        float s0b = 0.f, s1b = 0.f, s2b = 0.f;
#pragma unroll
        for (int half = 0; half < 2; half++) {
            float4 qa4[8], qb4[8];
#pragma unroll
            for (int i = 0; i < 8; i++) {
                qa4[i] = *(const float4*)(qpa + half * 32 + i * 4);
                qb4[i] = *(const float4*)(qpb + half * 32 + i * 4);
            }
#pragma unroll
            for (int i = 0; i < 8; i++) {
                const int d = half * 32 + i * 4;
                const float4 v0 = *(const float4*)(K0 + d);
                const float4 v1 = *(const float4*)(K1 + d);
                const float4 v2 = *(const float4*)(K2 + d);
                s0a = fmaf(qa4[i].x, v0.x, s0a); s0a = fmaf(qa4[i].y, v0.y, s0a);
                s0a = fmaf(qa4[i].z, v0.z, s0a); s0a = fmaf(qa4[i].w, v0.w, s0a);
                s1a = fmaf(qa4[i].x, v1.x, s1a); s1a = fmaf(qa4[i].y, v1.y, s1a);
                s1a = fmaf(qa4[i].z, v1.z, s1a); s1a = fmaf(qa4[i].w, v1.w, s1a);
                s2a = fmaf(qa4[i].x, v2.x, s2a); s2a = fmaf(qa4[i].y, v2.y, s2a);
                s2a = fmaf(qa4[i].z, v2.z, s2a); s2a = fmaf(qa4[i].w, v2.w, s2a);
                s0b = fmaf(qb4[i].x, v0.x, s0b); s0b = fmaf(qb4[i].y, v0.y, s0b);
                s0b = fmaf(qb4[i].z, v0.z, s0b); s0b = fmaf(qb4[i].w, v0.w, s0b);
                s1b = fmaf(qb4[i].x, v1.x, s1b); s1b = fmaf(qb4[i].y, v1.y, s1b);
                s1b = fmaf(qb4[i].z, v1.z, s1b); s1b = fmaf(qb4[i].w, v1.w, s1b);
                s2b = fmaf(qb4[i].x, v2.x, s2b); s2b = fmaf(qb4[i].y, v2.y, s2b);
                s2b = fmaf(qb4[i].z, v2.z, s2b); s2b = fmaf(qb4[i].w, v2.w, s2b);
            }
        }
        s0a *= scale; s1a *= scale; s2a *= scale;
        s0b *= scale; s1b *= scale; s2b *= scale;

        const bool isTxt2 = (lane < 13);
        float ma = fmaxf(s0a, s1a); if (isTxt2) ma = fmaxf(ma, s2a);
        float mb = fmaxf(s0b, s1b); if (isTxt2) mb = fmaxf(mb, s2b);
#pragma unroll
        for (int off = 16; off > 0; off >>= 1) {
            ma = fmaxf(ma, __shfl_xor_sync(0xffffffffu, ma, off));
            mb = fmaxf(mb, __shfl_xor_sync(0xffffffffu, mb, off));
        }
        const float e0a = __expf(s0a - ma), e1a = __expf(s1a - ma);
        const float e2a = isTxt2 ? __expf(s2a - ma) : 0.f;
        const float e0b = __expf(s0b - mb), e1b = __expf(s1b - mb);
        const float e2b = isTxt2 ? __expf(s2b - mb) : 0.f;
        float ta = e0a + e1a + e2a, tb = e0b + e1b + e2b;
#pragma unroll
        for (int off = 16; off > 0; off >>= 1) {
            ta += __shfl_xor_sync(0xffffffffu, ta, off);
            tb += __shfl_xor_sync(0xffffffffu, tb, off);
        }
        const float ia = 1.f / ta, ib = 1.f / tb;

        float ga = s2a, gb = s2b;
        ga = fmaxf(ga, __shfl_xor_sync(0xffffffffu, ga, 1));
        ga = fmaxf(ga, __shfl_xor_sync(0xffffffffu, ga, 2));
        gb = fmaxf(gb, __shfl_xor_sync(0xffffffffu, gb, 1));
        gb = fmaxf(gb, __shfl_xor_sync(0xffffffffu, gb, 2));
        const float ega = __expf(s2a - ga), egb = __expf(s2b - gb);
        float gsa = ega, gsb = egb;
        gsa += __shfl_xor_sync(0xffffffffu, gsa, 1);
        gsa += __shfl_xor_sync(0xffffffffu, gsa, 2);
        gsb += __shfl_xor_sync(0xffffffffu, gsb, 1);
        gsb += __shfl_xor_sync(0xffffffffu, gsb, 2);
        const float pga = ega / gsa, pgb = egb / gsb;

        Pa[lane] = e0a * ia;      Pb[lane] = e0b * ib;
        Pa[lane + 32] = e1a * ia; Pb[lane + 32] = e1b * ib;
        if (isTxt2) { Pa[lane + 64] = e2a * ia; Pb[lane + 64] = e2b * ib; }
        if (lane >= 24) { Pa[lane + 53] = pga; Pb[lane + 53] = pgb; }
        __syncwarp();

        float o0a = 0.f, o1a = 0.f, o0b = 0.f, o1b = 0.f;
#pragma unroll 5
        for (int k = 0; k < LTOT; k++) {
            const float v0 = Vsh[k * KPAD + lane];
            const float v1 = Vsh[k * KPAD + lane + 32];
            const float pa = Pa[k], pb = Pb[k];
            o0a = fmaf(pa, v0, o0a); o1a = fmaf(pa, v1, o1a);
            o0b = fmaf(pb, v0, o0b); o1b = fmaf(pb, v1, o1b);
        }

        const long long basea = ((long long)b * S_ + s) * C_ + h * D_;
        const long long baseb = basea + C_;
        const __nv_bfloat16 h0a = __float2bfloat16(o0a);
        const __nv_bfloat16 h1a = __float2bfloat16(o1a);
        const __nv_bfloat16 h0b = __float2bfloat16(o0b);
        const __nv_bfloat16 h1b = __float2bfloat16(o1b);
        ohi[basea + lane]      = h0a;
        ohi[basea + lane + 32] = h1a;
        ohi[baseb + lane]      = h0b;
        ohi[baseb + lane + 32] = h1b;
        olo[basea + lane]      = __float2bfloat16(o0a - __bfloat162float(h0a));
        olo[basea + lane + 32] = __float2bfloat16(o1a - __bfloat162float(h1a));
        olo[baseb + lane]      = __float2bfloat16(o0b - __bfloat162float(h0b));
        olo[baseb + lane + 32] = __float2bfloat16(o1b - __bfloat162float(h1b));
        __syncwarp();
    }
}

// ---------------------------------------------------------------------------
// Launch
// ---------------------------------------------------------------------------
extern "C" void kernel_launch(void* const* d_in, const int* in_sizes, int n_in,
                              void* d_out, int out_size) {
    const float* hidden = (const float*)d_in[0];
    const float* enc    = (const float*)d_in[1];
    const float* Wq     = (const float*)d_in[2];
    const float* Wk     = (const float*)d_in[3];
    const float* Wv     = (const float*)d_in[4];
    const float* Wk_ip  = (const float*)d_in[5];
    const float* Wv_ip  = (const float*)d_in[6];
    const float* Wk_lbl = (const float*)d_in[7];
    const float* Wv_lbl = (const float*)d_in[8];
    const float* Wo     = (const float*)d_in[9];
    const float* bo     = (const float*)d_in[10];
    float* out = (float*)d_out;

    float *qb, *kb, *vb;
    __nv_bfloat16 *ahi, *alo, *wqhi, *wqlo, *wohi, *wolo;
    cudaGetSymbolAddress((void**)&qb, g_q);
    cudaGetSymbolAddress((void**)&kb, g_k);
    cudaGetSymbolAddress((void**)&vb, g_v);
    cudaGetSymbolAddress((void**)&ahi, g_ahi);
    cudaGetSymbolAddress((void**)&alo, g_alo);
    cudaGetSymbolAddress((void**)&wqhi, g_wqhi);
    cudaGetSymbolAddress((void**)&wqlo, g_wqlo);
    cudaGetSymbolAddress((void**)&wohi, g_wohi);
    cudaGetSymbolAddress((void**)&wolo, g_wolo);

    cudaFuncSetAttribute(gemm_mma, cudaFuncAttributeMaxDynamicSharedMemorySize,
                         SMEM_GEMM);
    cudaFuncSetAttribute(attn_kernel, cudaFuncAttributeMaxDynamicSharedMemorySize,
                         ATTN_SMEM);

    // 1. Convert hidden + weights to bf16 hi/lo
    {
        const long long n4 = (long long)MTOT * C_ / 4;
        conv_split<<<(unsigned)((n4 + 255) / 256), 256>>>(hidden, ahi, alo, n4);
        dim3 gw(C_ / 32, C_ / 32), bw(32, 8);
        conv_w_t<<<gw, bw>>>(Wq, wqhi, wqlo);
        conv_w_t<<<gw, bw>>>(Wo, wohi, wolo);
    }

    // 2. Q projection
    gemm_mma<<<dim3(C_ / 256, MTOT / 128), 256, SMEM_GEMM>>>(
        ahi, alo, wqhi, wqlo, qb, nullptr, nullptr);

    // 3. KV projections
    {
        cudaMemsetAsync(kb, 0, (size_t)B_ * LTOT * C_ * sizeof(float));
        cudaMemsetAsync(vb, 0, (size_t)B_ * LTOT * C_ * sizeof(float));
        const long long sA = (long long)LTOT * DC_;
        const long long sC = (long long)LTOT * C_;
        dim3 blk(256);
        dim3 gT(C_ / 64, 3 * KSPLIT, B_);
        dim3 gS(C_ / 64, 1 * KSPLIT, B_);
        sgemm32s<<<gT, blk>>>(enc, Wk, kb, LTXT, sA, sC);
        sgemm32s<<<gT, blk>>>(enc, Wv, vb, LTXT, sA, sC);
        sgemm32s<<<gS, blk>>>(enc + (long long)LTXT * DC_, Wk_ip,
                              kb + (long long)LTXT * C_, LIMG, sA, sC);
        sgemm32s<<<gS, blk>>>(enc + (long long)LTXT * DC_, Wv_ip,
                              vb + (long long)LTXT * C_, LIMG, sA, sC);
        sgemm32s<<<gS, blk>>>(enc + (long long)(LTXT + LIMG) * DC_, Wk_lbl,
                              kb + (long long)(LTXT + LIMG) * C_, LLBL, sA, sC);
        sgemm32s<<<gS, blk>>>(enc + (long long)(LTXT + LIMG) * DC_, Wv_lbl,
                              vb + (long long)(LTXT + LIMG) * C_, LLBL, sA, sC);
    }

    // 4. Attention -> bf16 hi/lo
    attn_kernel<<<dim3(B_ * H_, 16), 256, ATTN_SMEM>>>(qb, kb, vb, ahi, alo);

    // 5. Output projection + bias + residual
    gemm_mma<<<dim3(C_ / 256, MTOT / 128), 256, SMEM_GEMM>>>(
        ahi, alo, wohi, wolo, out, bo, hidden);
}

// round 8
// speedup vs baseline: 2.3300x; 1.0105x over previous
#include <cuda_runtime.h>
#include <cuda_bf16.h>
#include <cstdint>

// Problem dims
#define B_   4
#define S_   4096
#define C_   1280
#define DC_  2048
#define H_   20
#define D_   64
#define LTXT 77
#define LIMG 4
#define LLBL 4
#define LTOT 85
#define KPAD 68
#define MTOT (B_ * S_)   // 16384

// ---------------------------------------------------------------------------
// Device scratch
// ---------------------------------------------------------------------------
__device__ float g_q[(size_t)MTOT * C_];
__device__ __nv_bfloat16 g_ahi[(size_t)MTOT * C_];
__device__ __nv_bfloat16 g_alo[(size_t)MTOT * C_];
__device__ __nv_bfloat16 g_wqhi[(size_t)C_ * C_];
__device__ __nv_bfloat16 g_wqlo[(size_t)C_ * C_];
__device__ __nv_bfloat16 g_wohi[(size_t)C_ * C_];
__device__ __nv_bfloat16 g_wolo[(size_t)C_ * C_];
__device__ float g_k[(size_t)B_ * LTOT * C_];
__device__ float g_v[(size_t)B_ * LTOT * C_];

// ---------------------------------------------------------------------------
// PTX helpers (stable ISA)
// ---------------------------------------------------------------------------
__device__ __forceinline__ uint32_t smem_u32(const void* p) {
    uint32_t a;
    asm("{ .reg .u64 t; cvta.to.shared.u64 t, %1; cvt.u32.u64 %0, t; }"
        : "=r"(a) : "l"(p));
    return a;
}
__device__ __forceinline__ void cp_async16(uint32_t dst, const void* src) {
    asm volatile("cp.async.cg.shared.global [%0], [%1], 16;" :: "r"(dst), "l"(src));
}
__device__ __forceinline__ void cp_commit() {
    asm volatile("cp.async.commit_group;");
}
__device__ __forceinline__ void cp_wait1() {
    asm volatile("cp.async.wait_group 1;");
}
__device__ __forceinline__ void ldsm_x4(uint32_t* r, uint32_t addr) {
    asm volatile("ldmatrix.sync.aligned.m8n8.x4.shared.b16 {%0,%1,%2,%3}, [%4];"
                 : "=r"(r[0]), "=r"(r[1]), "=r"(r[2]), "=r"(r[3]) : "r"(addr));
}
__device__ __forceinline__ void mma_bf16(float* c, const uint32_t* a,
                                         const uint32_t* b) {
    asm volatile(
        "mma.sync.aligned.m16n8k16.row.col.f32.bf16.bf16.f32 "
        "{%0,%1,%2,%3}, {%4,%5,%6,%7}, {%8,%9}, {%0,%1,%2,%3};"
        : "+f"(c[0]), "+f"(c[1]), "+f"(c[2]), "+f"(c[3])
        : "r"(a[0]), "r"(a[1]), "r"(a[2]), "r"(a[3]), "r"(b[0]), "r"(b[1]));
}

// ---------------------------------------------------------------------------
// Conversion kernels
// ---------------------------------------------------------------------------
__global__ void conv_split(const float* __restrict__ src,
                           __nv_bfloat16* __restrict__ hi,
                           __nv_bfloat16* __restrict__ lo, long long n4) {
    long long i = (long long)blockIdx.x * blockDim.x + threadIdx.x;
    if (i >= n4) return;
    float4 v = ((const float4*)src)[i];
    __nv_bfloat16 h[4], l[4];
    float f[4] = {v.x, v.y, v.z, v.w};
#pragma unroll
    for (int j = 0; j < 4; j++) {
        h[j] = __float2bfloat16(f[j]);
        l[j] = __float2bfloat16(f[j] - __bfloat162float(h[j]));
    }
    ((uint2*)hi)[i] = *(uint2*)h;
    ((uint2*)lo)[i] = *(uint2*)l;
}

__global__ void conv_w_t(const float* __restrict__ W,
                         __nv_bfloat16* __restrict__ Thi,
                         __nv_bfloat16* __restrict__ Tlo) {
    __shared__ float t[32][33];
    const int n0 = blockIdx.x * 32, k0 = blockIdx.y * 32;
    const int tx = threadIdx.x, ty = threadIdx.y;  // 32 x 8
#pragma unroll
    for (int i = 0; i < 4; i++) {
        const int kk = ty + 8 * i;
        t[kk][tx] = W[(long long)(k0 + kk) * C_ + n0 + tx];
    }
    __syncthreads();
#pragma unroll
    for (int i = 0; i < 4; i++) {
        const int nn = ty + 8 * i;
        const float v = t[tx][nn];
        const __nv_bfloat16 h = __float2bfloat16(v);
        const long long o = (long long)(n0 + nn) * C_ + k0 + tx;
        Thi[o] = h;
        Tlo[o] = __float2bfloat16(v - __bfloat162float(h));
    }
}

// ---------------------------------------------------------------------------
// bf16 split-precision GEMM v3 via mma.sync.
// CTA 128x128, 8 warps, warp tile 64x32. BK=32, 3-stage cp.async pipeline,
// register-double-buffered operands: per iteration all 24 LDSM (both k-halves)
// issue before the 96 MMAs, so LDSM latency hides behind tensor work.
// MMAs ordered product-major to avoid same-accumulator chains.
// ---------------------------------------------------------------------------
#define GK     C_            // 1280
#define NIT    (GK / 32)     // 40
#define ROWB   40            // bf16 per smem row (32 + 8 pad) = 80 B
#define TILEB  (128 * ROWB * 2)          // 10240
#define STAGEB (4 * TILEB)               // Ahi, Alo, Bhi, Blo = 40960
#define NSTAGE 3
#define SMEM_GEMM (NSTAGE * STAGEB)      // 122880

__device__ __forceinline__ void gemm_issue_stage(
    uint32_t sbase, const __nv_bfloat16* Ahi, const __nv_bfloat16* Alo,
    const __nv_bfloat16* Bhi, const __nv_bfloat16* Blo,
    int bm, int bn, int k0, int tid)
{
    const __nv_bfloat16* srcs[4] = {Ahi + (long long)bm * GK,
                                    Alo + (long long)bm * GK,
                                    Bhi + (long long)bn * GK,
                                    Blo + (long long)bn * GK};
#pragma unroll
    for (int t = 0; t < 4; t++) {
#pragma unroll
        for (int i = 0; i < 2; i++) {
            const int c   = tid + 256 * i;       // 0..511
            const int row = c >> 2;
            const int ch  = c & 3;
            cp_async16(sbase + t * TILEB + row * 80 + ch * 16,
                       srcs[t] + (long long)row * GK + k0 + ch * 8);
        }
    }
    cp_commit();
}

__global__ __launch_bounds__(256, 1)
void gemm_mma(const __nv_bfloat16* __restrict__ Ahi,
              const __nv_bfloat16* __restrict__ Alo,
              const __nv_bfloat16* __restrict__ Bhi,
              const __nv_bfloat16* __restrict__ Blo,
              float* __restrict__ Cout,
              const float* __restrict__ bias,
              const float* __restrict__ resid)
{
    extern __shared__ char smem[];
    const int tid  = threadIdx.x;
    const int warp = tid >> 5;
    const int lane = tid & 31;
    const int bm   = blockIdx.y * 128;
    const int bn   = blockIdx.x * 128;
    const uint32_t sb = smem_u32(smem);

    const int wm = (warp >> 2) * 64;   // 0 or 64
    const int wn = (warp & 3) * 32;    // 0,32,64,96

    float acc[4][4][4];
#pragma unroll
    for (int i = 0; i < 4; i++)
#pragma unroll
        for (int j = 0; j < 4; j++)
#pragma unroll
            for (int e = 0; e < 4; e++) acc[i][j][e] = 0.f;

    const int lmat = lane >> 3;   // 0..3
    const int lrow = lane & 7;
    // A x4: row = wm + i*16 + (lmat&1)*8 + lrow, col = ks*16 + (lmat>>1)*8
    const int aRow  = (lmat & 1) * 8 + lrow;
    const int aKoff = (lmat >> 1) * 8;
    // B x4 (n-pair jp): row = wn + jp*16 + (lmat>>1)*8 + lrow, col = ks*16 + (lmat&1)*8
    const int bRow  = (lmat >> 1) * 8 + lrow;
    const int bKoff = (lmat & 1) * 8;

    gemm_issue_stage(sb + 0 * STAGEB, Ahi, Alo, Bhi, Blo, bm, bn, 0, tid);
    gemm_issue_stage(sb + 1 * STAGEB, Ahi, Alo, Bhi, Blo, bm, bn, 32, tid);

    int stage = 0;
    for (int it = 0; it < NIT; it++) {
        cp_wait1();
        __syncthreads();
        if (it + 2 < NIT) {
            int ns = stage + 2; if (ns >= NSTAGE) ns -= NSTAGE;
            gemm_issue_stage(sb + ns * STAGEB, Ahi, Alo, Bhi, Blo,
                             bm, bn, (it + 2) * 32, tid);
        } else {
            cp_commit();
        }

        const uint32_t st  = sb + stage * STAGEB;
        const uint32_t sAh = st, sAl = st + TILEB;
        const uint32_t sBh = st + 2 * TILEB, sBl = st + 3 * TILEB;

        // ---- issue ALL ldmatrix for both k-halves up front ----
        uint32_t ah[2][4][4], al[2][4][4], bh[2][2][4], bl[2][2][4];
#pragma unroll
        for (int ks = 0; ks < 2; ks++) {
#pragma unroll
            for (int i = 0; i < 4; i++) {
                const uint32_t off =
                    (uint32_t)(wm + i * 16 + aRow) * 80 +
                    (uint32_t)(ks * 16 + aKoff) * 2;
                ldsm_x4(ah[ks][i], sAh + off);
                ldsm_x4(al[ks][i], sAl + off);
            }
#pragma unroll
            for (int jp = 0; jp < 2; jp++) {
                const uint32_t off =
                    (uint32_t)(wn + jp * 16 + bRow) * 80 +
                    (uint32_t)(ks * 16 + bKoff) * 2;
                ldsm_x4(bh[ks][jp], sBh + off);
                ldsm_x4(bl[ks][jp], sBl + off);
            }
        }

        // ---- MMAs, product-major (no same-acc back-to-back) ----
#pragma unroll
        for (int ks = 0; ks < 2; ks++) {
#pragma unroll
            for (int i = 0; i < 4; i++)
#pragma unroll
                for (int jp = 0; jp < 2; jp++) {
                    mma_bf16(acc[i][2 * jp],     ah[ks][i], &bh[ks][jp][0]);
                    mma_bf16(acc[i][2 * jp + 1], ah[ks][i], &bh[ks][jp][2]);
                }
#pragma unroll
            for (int i = 0; i < 4; i++)
#pragma unroll
                for (int jp = 0; jp < 2; jp++) {
                    mma_bf16(acc[i][2 * jp],     ah[ks][i], &bl[ks][jp][0]);
                    mma_bf16(acc[i][2 * jp + 1], ah[ks][i], &bl[ks][jp][2]);
                }
#pragma unroll
            for (int i = 0; i < 4; i++)
#pragma unroll
                for (int jp = 0; jp < 2; jp++) {
                    mma_bf16(acc[i][2 * jp],     al[ks][i], &bh[ks][jp][0]);
                    mma_bf16(acc[i][2 * jp + 1], al[ks][i], &bh[ks][jp][2]);
                }
        }
        if (++stage == NSTAGE) stage = 0;
    }

    // epilogue: acc -> gmem fp32 (+bias)(+resid)
#pragma unroll
    for (int i = 0; i < 4; i++) {
#pragma unroll
        for (int j = 0; j < 4; j++) {
            const int col = bn + wn + j * 8 + (lane & 3) * 2;
#pragma unroll
            for (int half = 0; half < 2; half++) {
                const long long row = bm + wm + i * 16 + (lane >> 2) + half * 8;
                float2 o;
                o.x = acc[i][j][half * 2 + 0];
                o.y = acc[i][j][half * 2 + 1];
                if (bias) { o.x += bias[col]; o.y += bias[col + 1]; }
                if (resid) {
                    const float2 rv = *(const float2*)(resid + row * C_ + col);
                    o.x += rv.x; o.y += rv.y;
                }
                *(float2*)(Cout + row * C_ + col) = o;
            }
        }
    }
}

// ---------------------------------------------------------------------------
// Split-K thin GEMM for KV projections (atomicAdd into zeroed output).
// ---------------------------------------------------------------------------
#define KSPLIT 8
#define KCHUNK (DC_ / KSPLIT)

__global__ __launch_bounds__(256)
void sgemm32s(const float* __restrict__ Abase,
              const float* __restrict__ Bw,
              float* __restrict__ Cbase,
              int M, long long strideA, long long strideC) {
    __shared__ float As[32][33];
    __shared__ float Bs[32][64];

    const float* A = Abase + (long long)blockIdx.z * strideA;
    float*       Cc = Cbase + (long long)blockIdx.z * strideC;

    const int rt = blockIdx.y / KSPLIT;
    const int ks = blockIdx.y % KSPLIT;
    const int bm = rt * 32;
    const int bn = blockIdx.x * 64;
    const int kc0 = ks * KCHUNK;

    const int tid = threadIdx.x;
    const int tx = tid & 15, ty = tid >> 4;
    const int aRow = tid >> 3, aCol = (tid & 7) << 2;
    const int bRow = tid >> 4, bCol = (tid & 15) << 2;

    float acc[2][4];
#pragma unroll
    for (int i = 0; i < 2; i++)
#pragma unroll
        for (int j = 0; j < 4; j++) acc[i][j] = 0.f;

    for (int k0 = kc0; k0 < kc0 + KCHUNK; k0 += 32) {
        float4 av = make_float4(0.f, 0.f, 0.f, 0.f);
        if (bm + aRow < M)
            av = *(const float4*)(A + (long long)(bm + aRow) * DC_ + k0 + aCol);
        As[aCol + 0][aRow] = av.x;
        As[aCol + 1][aRow] = av.y;
        As[aCol + 2][aRow] = av.z;
        As[aCol + 3][aRow] = av.w;
#pragma unroll
        for (int p = 0; p < 2; p++) {
            const int r = bRow + p * 16;
            *(float4*)&Bs[r][bCol] =
                *(const float4*)(Bw + (long long)(k0 + r) * C_ + bn + bCol);
        }
        __syncthreads();
#pragma unroll
        for (int kk = 0; kk < 32; kk++) {
            const float a0 = As[kk][ty * 2];
            const float a1 = As[kk][ty * 2 + 1];
            const float4 b = *(const float4*)&Bs[kk][tx * 4];
            acc[0][0] = fmaf(a0, b.x, acc[0][0]);
            acc[0][1] = fmaf(a0, b.y, acc[0][1]);
            acc[0][2] = fmaf(a0, b.z, acc[0][2]);
            acc[0][3] = fmaf(a0, b.w, acc[0][3]);
            acc[1][0] = fmaf(a1, b.x, acc[1][0]);
            acc[1][1] = fmaf(a1, b.y, acc[1][1]);
            acc[1][2] = fmaf(a1, b.z, acc[1][2]);
            acc[1][3] = fmaf(a1, b.w, acc[1][3]);
        }
        __syncthreads();
    }

#pragma unroll
    for (int i = 0; i < 2; i++) {
        const int r = bm + ty * 2 + i;
        if (r < M) {
            float* cp = Cc + (long long)r * C_ + bn + tx * 4;
#pragma unroll
            for (int j = 0; j < 4; j++) atomicAdd(cp + j, acc[i][j]);
        }
    }
}

// ---------------------------------------------------------------------------
// Fused 3-branch cross-attention (unchanged).
// ---------------------------------------------------------------------------
#define ATTN_SMEM ((2 * LTOT * KPAD + 8 * 2 * 88) * 4)

__global__ __launch_bounds__(256, 2)
void attn_kernel(const float* __restrict__ q,
                 const float* __restrict__ kall,
                 const float* __restrict__ vall,
                 __nv_bfloat16* __restrict__ ohi,
                 __nv_bfloat16* __restrict__ olo) {
    extern __shared__ float sm[];
    float* Ksh = sm;
    float* Vsh = sm + LTOT * KPAD;
    float* Pall = sm + 2 * LTOT * KPAD;

    const int bh = blockIdx.x;
    const int b = bh / H_, h = bh % H_;
    const int tid = threadIdx.x, lane = tid & 31, warp = tid >> 5;

    for (int i = tid; i < LTOT * D_; i += 256) {
        const int l = i >> 6, d = i & 63;
        const long long g = ((long long)b * LTOT + l) * C_ + h * D_ + d;
        Ksh[l * KPAD + d] = kall[g];
        Vsh[l * KPAD + d] = vall[g];
    }
    __syncthreads();

    const int sPer = S_ / gridDim.y;
    const int s0 = blockIdx.y * sPer;
    const float scale = 0.125f;

    const int k2 = (lane < 13) ? (64 + lane) : ((lane >= 24) ? (53 + lane) : 0);
    const float* K0 = Ksh + lane * KPAD;
    const float* K1 = Ksh + (lane + 32) * KPAD;
    const float* K2 = Ksh + k2 * KPAD;
    float* Pa = Pall + (warp * 2 + 0) * 88;
    float* Pb = Pall + (warp * 2 + 1) * 88;

    for (int s = s0 + warp * 2; s < s0 + sPer; s += 16) {
        const float* qpa = q + ((long long)b * S_ + s) * C_ + h * D_;
        const float* qpb = qpa + C_;

        float s0a = 0.f, s1a = 0.f, s2a = 0.f;
        float s0b = 0.f, s1b = 0.f, s2b = 0.f;
#pragma unroll
        for (int half = 0; half < 2; half++) {
            float4 qa4[8], qb4[8];
#pragma unroll
            for (int i = 0; i < 8; i++) {
                qa4[i] = *(const float4*)(qpa + half * 32 + i * 4);
                qb4[i] = *(const float4*)(qpb + half * 32 + i * 4);
            }
#pragma unroll
            for (int i = 0; i < 8; i++) {
                const int d = half * 32 + i * 4;
                const float4 v0 = *(const float4*)(K0 + d);
                const float4 v1 = *(const float4*)(K1 + d);
                const float4 v2 = *(const float4*)(K2 + d);
                s0a = fmaf(qa4[i].x, v0.x, s0a); s0a = fmaf(qa4[i].y, v0.y, s0a);
                s0a = fmaf(qa4[i].z, v0.z, s0a); s0a = fmaf(qa4[i].w, v0.w, s0a);
                s1a = fmaf(qa4[i].x, v1.x, s1a); s1a = fmaf(qa4[i].y, v1.y, s1a);
                s1a = fmaf(qa4[i].z, v1.z, s1a); s1a = fmaf(qa4[i].w, v1.w, s1a);
                s2a = fmaf(qa4[i].x, v2.x, s2a); s2a = fmaf(qa4[i].y, v2.y, s2a);
                s2a = fmaf(qa4[i].z, v2.z, s2a); s2a = fmaf(qa4[i].w, v2.w, s2a);
                s0b = fmaf(qb4[i].x, v0.x, s0b); s0b = fmaf(qb4[i].y, v0.y, s0b);
                s0b = fmaf(qb4[i].z, v0.z, s0b); s0b = fmaf(qb4[i].w, v0.w, s0b);
                s1b = fmaf(qb4[i].x, v1.x, s1b); s1b = fmaf(qb4[i].y, v1.y, s1b);
                s1b = fmaf(qb4[i].z, v1.z, s1b); s1b = fmaf(qb4[i].w, v1.w, s1b);
                s2b = fmaf(qb4[i].x, v2.x, s2b); s2b = fmaf(qb4[i].y, v2.y, s2b);
                s2b = fmaf(qb4[i].z, v2.z, s2b); s2b = fmaf(qb4[i].w, v2.w, s2b);
            }
        }
        s0a *= scale; s1a *= scale; s2a *= scale;
        s0b *= scale; s1b *= scale; s2b *= scale;

        const bool isTxt2 = (lane < 13);
        float ma = fmaxf(s0a, s1a); if (isTxt2) ma = fmaxf(ma, s2a);
        float mb = fmaxf(s0b, s1b); if (isTxt2) mb = fmaxf(mb, s2b);
#pragma unroll
        for (int off = 16; off > 0; off >>= 1) {
            ma = fmaxf(ma, __shfl_xor_sync(0xffffffffu, ma, off));
            mb = fmaxf(mb, __shfl_xor_sync(0xffffffffu, mb, off));
        }
        const float e0a = __expf(s0a - ma), e1a = __expf(s1a - ma);
        const float e2a = isTxt2 ? __expf(s2a - ma) : 0.f;
        const float e0b = __expf(s0b - mb), e1b = __expf(s1b - mb);
        const float e2b = isTxt2 ? __expf(s2b - mb) : 0.f;
        float ta = e0a + e1a + e2a, tb = e0b + e1b + e2b;
#pragma unroll
        for (int off = 16; off > 0; off >>= 1) {
            ta += __shfl_xor_sync(0xffffffffu, ta, off);
            tb += __shfl_xor_sync(0xffffffffu, tb, off);
        }
        const float ia = 1.f / ta, ib = 1.f / tb;

        float ga = s2a, gb = s2b;
        ga = fmaxf(ga, __shfl_xor_sync(0xffffffffu, ga, 1));
        ga = fmaxf(ga, __shfl_xor_sync(0xffffffffu, ga, 2));
        gb = fmaxf(gb, __shfl_xor_sync(0xffffffffu, gb, 1));
        gb = fmaxf(gb, __shfl_xor_sync(0xffffffffu, gb, 2));
        const float ega = __expf(s2a - ga), egb = __expf(s2b - gb);
        float gsa = ega, gsb = egb;
        gsa += __shfl_xor_sync(0xffffffffu, gsa, 1);
        gsa += __shfl_xor_sync(0xffffffffu, gsa, 2);
        gsb += __shfl_xor_sync(0xffffffffu, gsb, 1);
        gsb += __shfl_xor_sync(0xffffffffu, gsb, 2);
        const float pga = ega / gsa, pgb = egb / gsb;

        Pa[lane] = e0a * ia;      Pb[lane] = e0b * ib;
        Pa[lane + 32] = e1a * ia; Pb[lane + 32] = e1b * ib;
        if (isTxt2) { Pa[lane + 64] = e2a * ia; Pb[lane + 64] = e2b * ib; }
        if (lane >= 24) { Pa[lane + 53] = pga; Pb[lane + 53] = pgb; }
        __syncwarp();

        float o0a = 0.f, o1a = 0.f, o0b = 0.f, o1b = 0.f;
#pragma unroll 5
        for (int k = 0; k < LTOT; k++) {
            const float v0 = Vsh[k * KPAD + lane];
            const float v1 = Vsh[k * KPAD + lane + 32];
            const float pa = Pa[k], pb = Pb[k];
            o0a = fmaf(pa, v0, o0a); o1a = fmaf(pa, v1, o1a);
            o0b = fmaf(pb, v0, o0b); o1b = fmaf(pb, v1, o1b);
        }

        const long long basea = ((long long)b * S_ + s) * C_ + h * D_;
        const long long baseb = basea + C_;
        const __nv_bfloat16 h0a = __float2bfloat16(o0a);
        const __nv_bfloat16 h1a = __float2bfloat16(o1a);
        const __nv_bfloat16 h0b = __float2bfloat16(o0b);
        const __nv_bfloat16 h1b = __float2bfloat16(o1b);
        ohi[basea + lane]      = h0a;
        ohi[basea + lane + 32] = h1a;
        ohi[baseb + lane]      = h0b;
        ohi[baseb + lane + 32] = h1b;
        olo[basea + lane]      = __float2bfloat16(o0a - __bfloat162float(h0a));
        olo[basea + lane + 32] = __float2bfloat16(o1a - __bfloat162float(h1a));
        olo[baseb + lane]      = __float2bfloat16(o0b - __bfloat162float(h0b));
        olo[baseb + lane + 32] = __float2bfloat16(o1b - __bfloat162float(h1b));
        __syncwarp();
    }
}

// ---------------------------------------------------------------------------
// Launch
// ---------------------------------------------------------------------------
extern "C" void kernel_launch(void* const* d_in, const int* in_sizes, int n_in,
                              void* d_out, int out_size) {
    const float* hidden = (const float*)d_in[0];
    const float* enc    = (const float*)d_in[1];
    const float* Wq     = (const float*)d_in[2];
    const float* Wk     = (const float*)d_in[3];
    const float* Wv     = (const float*)d_in[4];
    const float* Wk_ip  = (const float*)d_in[5];
    const float* Wv_ip  = (const float*)d_in[6];
    const float* Wk_lbl = (const float*)d_in[7];
    const float* Wv_lbl = (const float*)d_in[8];
    const float* Wo     = (const float*)d_in[9];
    const float* bo     = (const float*)d_in[10];
    float* out = (float*)d_out;

    float *qb, *kb, *vb;
    __nv_bfloat16 *ahi, *alo, *wqhi, *wqlo, *wohi, *wolo;
    cudaGetSymbolAddress((void**)&qb, g_q);
    cudaGetSymbolAddress((void**)&kb, g_k);
    cudaGetSymbolAddress((void**)&vb, g_v);
    cudaGetSymbolAddress((void**)&ahi, g_ahi);
    cudaGetSymbolAddress((void**)&alo, g_alo);
    cudaGetSymbolAddress((void**)&wqhi, g_wqhi);
    cudaGetSymbolAddress((void**)&wqlo, g_wqlo);
    cudaGetSymbolAddress((void**)&wohi, g_wohi);
    cudaGetSymbolAddress((void**)&wolo, g_wolo);

    cudaFuncSetAttribute(gemm_mma, cudaFuncAttributeMaxDynamicSharedMemorySize,
                         SMEM_GEMM);
    cudaFuncSetAttribute(attn_kernel, cudaFuncAttributeMaxDynamicSharedMemorySize,
                         ATTN_SMEM);

    // 1. Convert hidden + weights to bf16 hi/lo
    {
        const long long n4 = (long long)MTOT * C_ / 4;
        conv_split<<<(unsigned)((n4 + 255) / 256), 256>>>(hidden, ahi, alo, n4);
        dim3 gw(C_ / 32, C_ / 32), bw(32, 8);
        conv_w_t<<<gw, bw>>>(Wq, wqhi, wqlo);
        conv_w_t<<<gw, bw>>>(Wo, wohi, wolo);
    }

    // 2. Q projection
    gemm_mma<<<dim3(C_ / 128, MTOT / 128), 256, SMEM_GEMM>>>(
        ahi, alo, wqhi, wqlo, qb, nullptr, nullptr);

    // 3. KV projections
    {
        cudaMemsetAsync(kb, 0, (size_t)B_ * LTOT * C_ * sizeof(float));
        cudaMemsetAsync(vb, 0, (size_t)B_ * LTOT * C_ * sizeof(float));
        const long long sA = (long long)LTOT * DC_;
        const long long sC = (long long)LTOT * C_;
        dim3 blk(256);
        dim3 gT(C_ / 64, 3 * KSPLIT, B_);
        dim3 gS(C_ / 64, 1 * KSPLIT, B_);
        sgemm32s<<<gT, blk>>>(enc, Wk, kb, LTXT, sA, sC);
        sgemm32s<<<gT, blk>>>(enc, Wv, vb, LTXT, sA, sC);
        sgemm32s<<<gS, blk>>>(enc + (long long)LTXT * DC_, Wk_ip,
                              kb + (long long)LTXT * C_, LIMG, sA, sC);
        sgemm32s<<<gS, blk>>>(enc + (long long)LTXT * DC_, Wv_ip,
                              vb + (long long)LTXT * C_, LIMG, sA, sC);
        sgemm32s<<<gS, blk>>>(enc + (long long)(LTXT + LIMG) * DC_, Wk_lbl,
                              kb + (long long)(LTXT + LIMG) * C_, LLBL, sA, sC);
        sgemm32s<<<gS, blk>>>(enc + (long long)(LTXT + LIMG) * DC_, Wv_lbl,
                              vb + (long long)(LTXT + LIMG) * C_, LLBL, sA, sC);
    }

    // 4. Attention -> bf16 hi/lo
    attn_kernel<<<dim3(B_ * H_, 16), 256, ATTN_SMEM>>>(qb, kb, vb, ahi, alo);

    // 5. Output projection + bias + residual
    gemm_mma<<<dim3(C_ / 128, MTOT / 128), 256, SMEM_GEMM>>>(
        ahi, alo, wohi, wolo, out, bo, hidden);
}